// round 11
// baseline (speedup 1.0000x reference)
#include <cuda_runtime.h>
#include <cuda_bf16.h>
#include <math.h>
#include <stdint.h>

typedef __nv_bfloat16 bf16;

// ---------------- problem constants ----------------
#define NTOK_TOTAL 129024   // 5376 windows * 24 tokens
#define NWIN       5376
#define HEADS      6

// ---------------- scratch (device globals) ----------------
__device__ float g_x2  [(size_t)NTOK_TOTAL * 192];   // trunk after proj (fp32)
__device__ bf16  g_h   [(size_t)NTOK_TOTAL * 192];   // LN out (bf16, GEMM A)
// qkv in attention-native layout: [win][head][q|k|v][24][32]
__device__ bf16  g_qkv [(size_t)NTOK_TOTAL * 576];
// attn out in [win][head][24][32] layout
__device__ bf16  g_attn[(size_t)NTOK_TOTAL * 192];
__device__ bf16  g_hid [(size_t)NTOK_TOTAL * 768];
__device__ float g_bias6[HEADS * 576];               // bias[h][m][n] (transposed!)
// pre-transposed bf16 weights (K-major: Wt[N][K])
__device__ bf16 g_qkv_wt [576 * 192];
__device__ bf16 g_proj_wt[192 * 192];
__device__ bf16 g_w1t    [768 * 192];
__device__ bf16 g_w2t    [192 * 768];

// ---------------- helpers ----------------
__device__ __forceinline__ size_t token_src_offset(int t) {
    int wi = t / 24, n = t % 24;
    int i3 = n / 12, j3 = (n >> 1) % 6, k3 = n & 1;
    int d0 = wi % 7;  int r = wi / 7;
    int w0 = r % 16;  r /= 16;
    int h0 = r % 24;  int b0 = r / 24;
    return ((((size_t)b0 * 48 + (h0 * 2 + i3)) * 96 + (w0 * 6 + j3)) * 14
            + (d0 * 2 + k3)) * 192;
}
__device__ __forceinline__ float warp_sum(float v) {
#pragma unroll
    for (int o = 16; o; o >>= 1) v += __shfl_xor_sync(0xffffffffu, v, o);
    return v;
}
__device__ __forceinline__ uint32_t smem_u32(const void* p) {
    uint32_t a;
    asm("{ .reg .u64 t; cvta.to.shared.u64 t, %1; cvt.u32.u64 %0, t; }" : "=r"(a) : "l"(p));
    return a;
}
__device__ __forceinline__ void cp16(uint32_t dst, const void* src) {
    asm volatile("cp.async.cg.shared.global [%0], [%1], 16;" :: "r"(dst), "l"(src));
}
#define CP_COMMIT() asm volatile("cp.async.commit_group;" ::: "memory")
#define CP_WAIT(n)  asm volatile("cp.async.wait_group %0;" :: "n"(n) : "memory")

__device__ __forceinline__ void ldsm_x4(uint32_t* r, uint32_t a) {
    asm volatile("ldmatrix.sync.aligned.m8n8.x4.shared.b16 {%0,%1,%2,%3}, [%4];"
                 : "=r"(r[0]), "=r"(r[1]), "=r"(r[2]), "=r"(r[3]) : "r"(a));
}
__device__ __forceinline__ void mma_bf16(float* d, const uint32_t* a,
                                         const uint32_t* b, const float* c) {
    asm volatile(
        "mma.sync.aligned.m16n8k16.row.col.f32.bf16.bf16.f32 "
        "{%0,%1,%2,%3}, {%4,%5,%6,%7}, {%8,%9}, {%10,%11,%12,%13};"
        : "=f"(d[0]), "=f"(d[1]), "=f"(d[2]), "=f"(d[3])
        : "r"(a[0]), "r"(a[1]), "r"(a[2]), "r"(a[3]),
          "r"(b[0]), "r"(b[1]),
          "f"(c[0]), "f"(c[1]), "f"(c[2]), "f"(c[3]));
}
__device__ __forceinline__ float2 bf2f2(uint32_t u) {
    __nv_bfloat162 b = *reinterpret_cast<__nv_bfloat162*>(&u);
    return __bfloat1622float2(b);
}
__device__ __forceinline__ uint32_t f2bf2u(float lo, float hi) {
    __nv_bfloat162 b = __floats2bfloat162_rn(lo, hi);
    return *reinterpret_cast<uint32_t*>(&b);
}

// ---------------- one-shot weight transpose (all 4 weights) ----------------
__global__ void transpose_all_kernel(
    const float* __restrict__ qkv_w, const float* __restrict__ proj_w,
    const float* __restrict__ w1, const float* __restrict__ w2,
    bf16* __restrict__ qkv_wt, bf16* __restrict__ proj_wt,
    bf16* __restrict__ w1t, bf16* __restrict__ w2t)
{
    __shared__ float t[32][33];
    int bid = blockIdx.x;
    const float* W; bf16* Wt; int K, N, loc;
    if (bid < 108)      { W = qkv_w;  Wt = qkv_wt;  K = 192; N = 576; loc = bid; }
    else if (bid < 144) { W = proj_w; Wt = proj_wt; K = 192; N = 192; loc = bid - 108; }
    else if (bid < 288) { W = w1;     Wt = w1t;     K = 192; N = 768; loc = bid - 144; }
    else                { W = w2;     Wt = w2t;     K = 768; N = 192; loc = bid - 288; }
    int Kt = K / 32;
    int kb = (loc % Kt) * 32, nb = (loc / Kt) * 32;
    int x = threadIdx.x, y = threadIdx.y;
#pragma unroll
    for (int j = 0; j < 32; j += 8) t[y + j][x] = W[(size_t)(kb + y + j) * N + nb + x];
    __syncthreads();
#pragma unroll
    for (int j = 0; j < 32; j += 8)
        Wt[(size_t)(nb + y + j) * K + kb + x] = __float2bfloat16(t[x][y + j]);
}

// ---------------- bias precompute (TRANSPOSED): bias6[h*576 + m*24 + n] -----
__global__ void bias_precompute_kernel(const float* __restrict__ bias_table,
                                       const int* __restrict__ rel_index)
{
    int h = blockIdx.x, idx = threadIdx.x;   // idx = m*24 + n
    if (idx < 576) {
        int m = idx / 24, n = idx - m * 24;
        g_bias6[h * 576 + idx] = bias_table[rel_index[n * 24 + m] * HEADS + h];
    }
}

// ---------------- gather + LN1 ----------------
__global__ __launch_bounds__(256) void gather_ln1_kernel(
    const float* __restrict__ x, const float* __restrict__ gam, const float* __restrict__ bet)
{
    int t = blockIdx.x * 8 + (threadIdx.x >> 5);
    int lane = threadIdx.x & 31;
    size_t src = token_src_offset(t);
    float v[6]; float s = 0.f;
#pragma unroll
    for (int q = 0; q < 6; q++) { v[q] = x[src + lane + q * 32]; s += v[q]; }
    float mean = warp_sum(s) * (1.0f / 192.0f);
    float vs = 0.f;
#pragma unroll
    for (int q = 0; q < 6; q++) { float d = v[q] - mean; vs += d * d; }
    float rstd = rsqrtf(warp_sum(vs) * (1.0f / 192.0f) + 1e-5f);
    size_t dst = (size_t)t * 192;
#pragma unroll
    for (int q = 0; q < 6; q++) {
        int c = lane + q * 32;
        g_h[dst + c] = __float2bfloat16((v[q] - mean) * rstd * gam[c] + bet[c]);
    }
}

// ---------------- attention: lane = query row, shfl-free softmax ------------
__global__ __launch_bounds__(256) void attn_kernel()
{
    __shared__ float k_s[8][768];   // [m*32 + d]
    __shared__ float v_s[8][768];
    const int w = threadIdx.x >> 5, lane = threadIdx.x & 31;
    const int pair = blockIdx.x * 8 + w;
    const int h = pair % 6;
    const bf16* base = g_qkv + (size_t)pair * 2304;   // [q 768 | k 768 | v 768]
    const float* bias = g_bias6 + h * 576;            // [m][n]

#pragma unroll
    for (int j = 0; j < 3; j++) {
        int idx = (lane + j * 32) * 8;
        uint4 uk = *(const uint4*)(base + 768 + idx);
        uint4 uv = *(const uint4*)(base + 1536 + idx);
        float2 f;
        f = bf2f2(uk.x); k_s[w][idx+0] = f.x; k_s[w][idx+1] = f.y;
        f = bf2f2(uk.y); k_s[w][idx+2] = f.x; k_s[w][idx+3] = f.y;
        f = bf2f2(uk.z); k_s[w][idx+4] = f.x; k_s[w][idx+5] = f.y;
        f = bf2f2(uk.w); k_s[w][idx+6] = f.x; k_s[w][idx+7] = f.y;
        f = bf2f2(uv.x); v_s[w][idx+0] = f.x; v_s[w][idx+1] = f.y;
        f = bf2f2(uv.y); v_s[w][idx+2] = f.x; v_s[w][idx+3] = f.y;
        f = bf2f2(uv.z); v_s[w][idx+4] = f.x; v_s[w][idx+5] = f.y;
        f = bf2f2(uv.w); v_s[w][idx+6] = f.x; v_s[w][idx+7] = f.y;
    }
    __syncwarp();

    if (lane < 24) {
        float q[32];
        const bf16* qp = base + lane * 32;
#pragma unroll
        for (int d = 0; d < 32; d += 8) {
            uint4 u = *(const uint4*)(qp + d);
            float2 f;
            f = bf2f2(u.x); q[d+0] = f.x; q[d+1] = f.y;
            f = bf2f2(u.y); q[d+2] = f.x; q[d+3] = f.y;
            f = bf2f2(u.z); q[d+4] = f.x; q[d+5] = f.y;
            f = bf2f2(u.w); q[d+6] = f.x; q[d+7] = f.y;
        }

        const float scale = 0.17677669529663687f;  // 32^-0.5
        float p[24];
        float mx = -1e30f;
#pragma unroll 4
        for (int m = 0; m < 24; m++) {
            float a = 0.f;
#pragma unroll
            for (int d = 0; d < 32; d += 4) {
                float4 k4 = *(const float4*)&k_s[w][m * 32 + d];
                a = fmaf(q[d],   k4.x, a); a = fmaf(q[d+1], k4.y, a);
                a = fmaf(q[d+2], k4.z, a); a = fmaf(q[d+3], k4.w, a);
            }
            a = a * scale + bias[m * 24 + lane];
            p[m] = a;
            mx = fmaxf(mx, a);
        }
        float sm = 0.f;
#pragma unroll
        for (int m = 0; m < 24; m++) { p[m] = __expf(p[m] - mx); sm += p[m]; }
        float inv = 1.0f / sm;

        float o[32];
#pragma unroll
        for (int d = 0; d < 32; d++) o[d] = 0.f;
#pragma unroll 4
        for (int m = 0; m < 24; m++) {
            float pm = p[m];
#pragma unroll
            for (int d = 0; d < 32; d += 4) {
                float4 v4 = *(const float4*)&v_s[w][m * 32 + d];
                o[d]   = fmaf(pm, v4.x, o[d]);
                o[d+1] = fmaf(pm, v4.y, o[d+1]);
                o[d+2] = fmaf(pm, v4.z, o[d+2]);
                o[d+3] = fmaf(pm, v4.w, o[d+3]);
            }
        }
        bf16* ob = g_attn + (size_t)pair * 768 + lane * 32;
#pragma unroll
        for (int d = 0; d < 32; d += 8) {
            uint4 u;
            u.x = f2bf2u(o[d]*inv,   o[d+1]*inv);
            u.y = f2bf2u(o[d+2]*inv, o[d+3]*inv);
            u.z = f2bf2u(o[d+4]*inv, o[d+5]*inv);
            u.w = f2bf2u(o[d+6]*inv, o[d+7]*inv);
            *(uint4*)(ob + d) = u;
        }
    }
}

// ======================= generic bf16 GEMM (BN=96) ==========================
// 4-stage cp.async pipeline, hoisted ldsm addresses.
// EPI: 0 bias->bf16 scatter to qkv layout, 1 bias+gelu->bf16,
//      3 bias+res+scatter->fp32 output
#define GEMM_SMEM (4 * (128 + 96) * 40 * 2)
template <int EPI>
__global__ __launch_bounds__(256, 3) void tc_gemm(
    const bf16* __restrict__ A, const bf16* __restrict__ Bt,
    const float* __restrict__ bias, const float* __restrict__ res,
    void* __restrict__ Cc, int N, int K)
{
    constexpr int LDA = 40;
    constexpr int ASZ = 128 * LDA, BSZ = 96 * LDA;   // halves per buffer
    extern __shared__ bf16 smem[];
    bf16* Asb = smem;
    bf16* Bsb = smem + 4 * ASZ;

    const int tid  = threadIdx.x;
    const int lane = tid & 31;
    const int wid  = tid >> 5;
    const int wm   = wid & 3;
    const int wn   = wid >> 2;
    const int col0 = blockIdx.x * 96;
    const int row0 = blockIdx.y * 128;
    const int gq = lane >> 2, tg = lane & 3;

    const uint32_t sAb = smem_u32(Asb), sBb = smem_u32(Bsb);
    // hoisted ldsm bases (byte offsets within a buffer)
    const uint32_t a_rel = (uint32_t)(((wm * 32 + (lane & 15)) * LDA
                                       + (lane >> 4) * 8) * 2);
    uint32_t b_rel[3];
#pragma unroll
    for (int p = 0; p < 3; p++)
        b_rel[p] = (uint32_t)(((wn * 48 + p * 16 + (lane & 7) + ((lane >> 4) << 3)) * LDA
                              + ((lane >> 3) & 1) * 8) * 2);
    // cp.async dest offsets (per-thread, hoisted)
    const uint32_t cpa0 = (uint32_t)((tid >> 2) * 80 + (tid & 3) * 16);
    const uint32_t cpa1 = (uint32_t)(((tid + 256) >> 2) * 80 + (tid & 3) * 16);

    float acc[2][6][4];
#pragma unroll
    for (int mi = 0; mi < 2; mi++)
#pragma unroll
        for (int ni = 0; ni < 6; ni++)
#pragma unroll
            for (int j = 0; j < 4; j++) acc[mi][ni][j] = 0.f;

    const int nstages = K / 32;

    auto prefetch = [&](int s, int b) {
        const bf16* Ag = A + (size_t)row0 * K + s * 32;
        const bf16* Bg = Bt + (size_t)col0 * K + s * 32;
        uint32_t sA = sAb + (uint32_t)b * (ASZ * 2);
        uint32_t sB = sBb + (uint32_t)b * (BSZ * 2);
        cp16(sA + cpa0, Ag + (size_t)(tid >> 2) * K + (tid & 3) * 8);
        cp16(sA + cpa1, Ag + (size_t)((tid + 256) >> 2) * K + (tid & 3) * 8);
        cp16(sB + cpa0, Bg + (size_t)(tid >> 2) * K + (tid & 3) * 8);
        if (tid < 128)
            cp16(sB + cpa1, Bg + (size_t)((tid + 256) >> 2) * K + (tid & 3) * 8);
        CP_COMMIT();
    };

    prefetch(0, 0);
    prefetch(1, 1);
    if (nstages > 2) prefetch(2, 2);

    for (int s = 0; s < nstages; s++) {
        if (s + 2 < nstages)      CP_WAIT(2);
        else if (s + 1 < nstages) CP_WAIT(1);
        else                      CP_WAIT(0);
        __syncthreads();
        if (s + 3 < nstages) prefetch(s + 3, (s + 3) & 3);

        const int b = s & 3;
        const uint32_t sA = sAb + (uint32_t)b * (ASZ * 2) + a_rel;
        const uint32_t sBB = sBb + (uint32_t)b * (BSZ * 2);
#pragma unroll
        for (int kk = 0; kk < 32; kk += 16) {
            uint32_t afr[2][4];
#pragma unroll
            for (int mi = 0; mi < 2; mi++)
                ldsm_x4(afr[mi], sA + (uint32_t)(kk * 2 + mi * (16 * LDA * 2)));

            uint32_t bfr[6][2];
#pragma unroll
            for (int p = 0; p < 3; p++) {
                uint32_t r4[4];
                ldsm_x4(r4, sBB + b_rel[p] + (uint32_t)(kk * 2));
                bfr[2*p][0] = r4[0]; bfr[2*p][1] = r4[1];
                bfr[2*p+1][0] = r4[2]; bfr[2*p+1][1] = r4[3];
            }
#pragma unroll
            for (int mi = 0; mi < 2; mi++)
#pragma unroll
                for (int ni = 0; ni < 6; ni++)
                    mma_bf16(acc[mi][ni], afr[mi], bfr[ni], acc[mi][ni]);
        }
    }

#pragma unroll
    for (int mi = 0; mi < 2; mi++) {
#pragma unroll
        for (int ni = 0; ni < 6; ni++) {
            int row = row0 + wm * 32 + mi * 16 + gq;
            int col = col0 + wn * 48 + ni * 8 + tg * 2;
            float b0 = bias[col], b1 = bias[col + 1];
#pragma unroll
            for (int hh = 0; hh < 2; hh++) {
                int r = row + hh * 8;
                float v0 = acc[mi][ni][hh * 2]     + b0;
                float v1 = acc[mi][ni][hh * 2 + 1] + b1;
                if (EPI == 1) {
                    v0 = 0.5f * v0 * (1.0f + erff(v0 * 0.70710678118654752f));
                    v1 = 0.5f * v1 * (1.0f + erff(v1 * 0.70710678118654752f));
                }
                if (EPI == 0) {
                    int wi2 = r / 24, n2 = r - wi2 * 24;
                    int which = col / 192;
                    int rem = col - which * 192;
                    int h2 = rem >> 5, d2 = rem & 31;
                    bf16* cp_ = (bf16*)Cc +
                        ((((size_t)wi2 * 6 + h2) * 3 + which) * 768 + n2 * 32 + d2);
                    *(__nv_bfloat162*)cp_ = __floats2bfloat162_rn(v0, v1);
                } else if (EPI == 3) {
                    const float* rp = res + (size_t)r * 192 + col;
                    v0 += rp[0]; v1 += rp[1];
                    size_t off = token_src_offset(r) + col;
                    *(float2*)((float*)Cc + off) = make_float2(v0, v1);
                } else {
                    bf16* cp_ = (bf16*)Cc + (size_t)r * N + col;
                    *(__nv_bfloat162*)cp_ = __floats2bfloat162_rn(v0, v1);
                }
            }
        }
    }
}

// ===== proj GEMM (BM=64, BN=192) + residual(from x) + LN2, 3 CTAs/SM ========
#define PROJ_SMEM (3 * (64 + 192) * 40 * 2)
__global__ __launch_bounds__(256, 3) void proj_ln2_kernel(
    const bf16* __restrict__ A, const bf16* __restrict__ Bt,
    const float* __restrict__ bias, const float* __restrict__ x,
    const float* __restrict__ gam, const float* __restrict__ bet)
{
    constexpr int LDA = 40, K = 192;
    constexpr int ASZ = 64 * LDA, BSZ = 192 * LDA;
    extern __shared__ bf16 smem[];
    bf16* Asb = smem;
    bf16* Bsb = smem + 3 * ASZ;
    __shared__ float s_sum[64][4];
    __shared__ float s_sq [64][4];

    const int tid  = threadIdx.x;
    const int lane = tid & 31;
    const int wid  = tid >> 5;
    const int wm   = wid & 1;
    const int wn   = wid >> 1;
    const int row0 = blockIdx.x * 64;
    const int gq = lane >> 2, tg = lane & 3;

    const uint32_t sAb = smem_u32(Asb), sBb = smem_u32(Bsb);
    const uint32_t a_rel = (uint32_t)(((wm * 32 + (lane & 15)) * LDA
                                       + (lane >> 4) * 8) * 2);
    uint32_t b_rel[3];
#pragma unroll
    for (int p = 0; p < 3; p++)
        b_rel[p] = (uint32_t)(((wn * 48 + p * 16 + (lane & 7) + ((lane >> 4) << 3)) * LDA
                              + ((lane >> 3) & 1) * 8) * 2);

    float acc[2][6][4];
#pragma unroll
    for (int mi = 0; mi < 2; mi++)
#pragma unroll
        for (int ni = 0; ni < 6; ni++)
#pragma unroll
            for (int j = 0; j < 4; j++) acc[mi][ni][j] = 0.f;

    const int nstages = 6;

    auto prefetch = [&](int s, int b) {
        const bf16* Bg = Bt + (size_t)s * 32;
        uint32_t sA = sAb + (uint32_t)b * (ASZ * 2);
        uint32_t sB = sBb + (uint32_t)b * (BSZ * 2);
        {
            int r = tid >> 2, c4 = tid & 3;
            int rg = row0 + r;
            int win = rg / 24, n2 = rg - win * 24;
            const bf16* src = A + ((size_t)win * 6 + s) * 768 + n2 * 32 + c4 * 8;
            cp16(sA + (uint32_t)(r * 80 + c4 * 16), src);
        }
#pragma unroll
        for (int j = 0; j < 3; j++) {
            int idx = tid + j * 256;
            int r = idx >> 2, c = idx & 3;
            cp16(sB + (uint32_t)(r * 80 + c * 16), Bg + (size_t)r * K + c * 8);
        }
        CP_COMMIT();
    };

    prefetch(0, 0);
    prefetch(1, 1);

    for (int s = 0; s < nstages; s++) {
        if (s < nstages - 1) CP_WAIT(1); else CP_WAIT(0);
        __syncthreads();
        if (s + 2 < nstages) prefetch(s + 2, (s + 2) % 3);

        const int b = s % 3;
        const uint32_t sA = sAb + (uint32_t)b * (ASZ * 2) + a_rel;
        const uint32_t sBB = sBb + (uint32_t)b * (BSZ * 2);
#pragma unroll
        for (int kk = 0; kk < 32; kk += 16) {
            uint32_t afr[2][4];
#pragma unroll
            for (int mi = 0; mi < 2; mi++)
                ldsm_x4(afr[mi], sA + (uint32_t)(kk * 2 + mi * (16 * LDA * 2)));

            uint32_t bfr[6][2];
#pragma unroll
            for (int p = 0; p < 3; p++) {
                uint32_t r4[4];
                ldsm_x4(r4, sBB + b_rel[p] + (uint32_t)(kk * 2));
                bfr[2*p][0] = r4[0]; bfr[2*p][1] = r4[1];
                bfr[2*p+1][0] = r4[2]; bfr[2*p+1][1] = r4[3];
            }
#pragma unroll
            for (int mi = 0; mi < 2; mi++)
#pragma unroll
                for (int ni = 0; ni < 6; ni++)
                    mma_bf16(acc[mi][ni], afr[mi], bfr[ni], acc[mi][ni]);
        }
    }

    // ---- epilogue: bias + residual(from x) + row stats ----
#pragma unroll
    for (int mi = 0; mi < 2; mi++) {
#pragma unroll
        for (int hh = 0; hh < 2; hh++) {
            int rl = wm * 32 + mi * 16 + gq + hh * 8;
            int r  = row0 + rl;
            size_t roff = token_src_offset(r);
            float s1 = 0.f, s2 = 0.f;
#pragma unroll
            for (int ni = 0; ni < 6; ni++) {
                int col = wn * 48 + ni * 8 + tg * 2;
                float2 rx = *(const float2*)(x + roff + col);
                float v0 = acc[mi][ni][hh*2]     + bias[col]     + rx.x;
                float v1 = acc[mi][ni][hh*2 + 1] + bias[col + 1] + rx.y;
                acc[mi][ni][hh*2]     = v0;
                acc[mi][ni][hh*2 + 1] = v1;
                s1 += v0 + v1;
                s2 += v0 * v0 + v1 * v1;
            }
            s1 += __shfl_xor_sync(0xffffffffu, s1, 1);
            s1 += __shfl_xor_sync(0xffffffffu, s1, 2);
            s2 += __shfl_xor_sync(0xffffffffu, s2, 1);
            s2 += __shfl_xor_sync(0xffffffffu, s2, 2);
            if (tg == 0) { s_sum[rl][wn] = s1; s_sq[rl][wn] = s2; }
        }
    }
    __syncthreads();
#pragma unroll
    for (int mi = 0; mi < 2; mi++) {
#pragma unroll
        for (int hh = 0; hh < 2; hh++) {
            int rl = wm * 32 + mi * 16 + gq + hh * 8;
            int r  = row0 + rl;
            float S1 = s_sum[rl][0] + s_sum[rl][1] + s_sum[rl][2] + s_sum[rl][3];
            float S2 = s_sq [rl][0] + s_sq [rl][1] + s_sq [rl][2] + s_sq [rl][3];
            float mean = S1 * (1.0f / 192.0f);
            float var  = S2 * (1.0f / 192.0f) - mean * mean;
            float rstd = rsqrtf(var + 1e-5f);
#pragma unroll
            for (int ni = 0; ni < 6; ni++) {
                int col = wn * 48 + ni * 8 + tg * 2;
                float v0 = acc[mi][ni][hh*2], v1 = acc[mi][ni][hh*2 + 1];
                *(float2*)(g_x2 + (size_t)r * 192 + col) = make_float2(v0, v1);
                float n0 = (v0 - mean) * rstd * gam[col]     + bet[col];
                float n1 = (v1 - mean) * rstd * gam[col + 1] + bet[col + 1];
                *(__nv_bfloat162*)(g_h + (size_t)r * 192 + col) =
                    __floats2bfloat162_rn(n0, n1);
            }
        }
    }
}

// ---------------- host launcher ----------------
extern "C" void kernel_launch(void* const* d_in, const int* in_sizes, int n_in,
                              void* d_out, int out_size)
{
    const float* x      = (const float*)d_in[0];
    const float* ln1_g  = (const float*)d_in[1];
    const float* ln1_b  = (const float*)d_in[2];
    const float* qkv_w  = (const float*)d_in[3];
    const float* qkv_b  = (const float*)d_in[4];
    const float* btab   = (const float*)d_in[5];
    const float* proj_w = (const float*)d_in[6];
    const float* proj_b = (const float*)d_in[7];
    const float* ln2_g  = (const float*)d_in[8];
    const float* ln2_b  = (const float*)d_in[9];
    const float* mlp_w1 = (const float*)d_in[10];
    const float* mlp_b1 = (const float*)d_in[11];
    const float* mlp_w2 = (const float*)d_in[12];
    const float* mlp_b2 = (const float*)d_in[13];
    const int*   rel_idx= (const int*)d_in[14];
    float*       out    = (float*)d_out;

    bf16 *p_h, *p_qkv, *p_attn, *p_hid;
    float *p_x2;
    bf16 *p_qkv_wt, *p_proj_wt, *p_w1t, *p_w2t;
    cudaGetSymbolAddress((void**)&p_h,    g_h);
    cudaGetSymbolAddress((void**)&p_qkv,  g_qkv);
    cudaGetSymbolAddress((void**)&p_attn, g_attn);
    cudaGetSymbolAddress((void**)&p_x2,   g_x2);
    cudaGetSymbolAddress((void**)&p_hid,  g_hid);
    cudaGetSymbolAddress((void**)&p_qkv_wt,  g_qkv_wt);
    cudaGetSymbolAddress((void**)&p_proj_wt, g_proj_wt);
    cudaGetSymbolAddress((void**)&p_w1t,  g_w1t);
    cudaGetSymbolAddress((void**)&p_w2t,  g_w2t);

    cudaFuncSetAttribute(tc_gemm<0>, cudaFuncAttributeMaxDynamicSharedMemorySize, GEMM_SMEM);
    cudaFuncSetAttribute(tc_gemm<1>, cudaFuncAttributeMaxDynamicSharedMemorySize, GEMM_SMEM);
    cudaFuncSetAttribute(tc_gemm<3>, cudaFuncAttributeMaxDynamicSharedMemorySize, GEMM_SMEM);
    cudaFuncSetAttribute(proj_ln2_kernel, cudaFuncAttributeMaxDynamicSharedMemorySize, PROJ_SMEM);

    transpose_all_kernel<<<432, dim3(32, 8)>>>(qkv_w, proj_w, mlp_w1, mlp_w2,
                                               p_qkv_wt, p_proj_wt, p_w1t, p_w2t);
    bias_precompute_kernel<<<HEADS, 576>>>(btab, rel_idx);

    gather_ln1_kernel<<<NTOK_TOTAL / 8, 256>>>(x, ln1_g, ln1_b);

    const int Mb = NTOK_TOTAL / 128;  // 1008
    tc_gemm<0><<<dim3(6, Mb), 256, GEMM_SMEM>>>(p_h, p_qkv_wt, qkv_b, nullptr, p_qkv, 576, 192);
    attn_kernel<<<NWIN * HEADS / 8, 256>>>();
    proj_ln2_kernel<<<NTOK_TOTAL / 64, 256, PROJ_SMEM>>>(p_attn, p_proj_wt, proj_b, x, ln2_g, ln2_b);
    tc_gemm<1><<<dim3(8, Mb), 256, GEMM_SMEM>>>(p_h, p_w1t, mlp_b1, nullptr, p_hid, 768, 192);
    tc_gemm<3><<<dim3(2, Mb), 256, GEMM_SMEM>>>(p_hid, p_w2t, mlp_b2, p_x2, out, 192, 768);
}

// round 12
// speedup vs baseline: 1.0115x; 1.0115x over previous
#include <cuda_runtime.h>
#include <cuda_bf16.h>
#include <math.h>
#include <stdint.h>

typedef __nv_bfloat16 bf16;

// ---------------- problem constants ----------------
#define NTOK_TOTAL 129024   // 5376 windows * 24 tokens
#define NWIN       5376
#define HEADS      6

// ---------------- scratch (device globals) ----------------
__device__ float g_x2  [(size_t)NTOK_TOTAL * 192];   // trunk after proj (fp32)
__device__ bf16  g_h   [(size_t)NTOK_TOTAL * 192];   // LN out (bf16, GEMM A)
// qkv in attention-native layout: [win][head][q|k|v][24][32]
__device__ bf16  g_qkv [(size_t)NTOK_TOTAL * 576];
// attn out in [win][head][24][32] layout
__device__ bf16  g_attn[(size_t)NTOK_TOTAL * 192];
__device__ bf16  g_hid [(size_t)NTOK_TOTAL * 768];
__device__ float g_bias6[HEADS * 576];               // bias[h][m][n] (transposed!)
// pre-transposed bf16 weights (K-major: Wt[N][K])
__device__ bf16 g_qkv_wt [576 * 192];
__device__ bf16 g_proj_wt[192 * 192];
__device__ bf16 g_w1t    [768 * 192];
__device__ bf16 g_w2t    [192 * 768];

// ---------------- helpers ----------------
__device__ __forceinline__ size_t token_src_offset(int t) {
    int wi = t / 24, n = t % 24;
    int i3 = n / 12, j3 = (n >> 1) % 6, k3 = n & 1;
    int d0 = wi % 7;  int r = wi / 7;
    int w0 = r % 16;  r /= 16;
    int h0 = r % 24;  int b0 = r / 24;
    return ((((size_t)b0 * 48 + (h0 * 2 + i3)) * 96 + (w0 * 6 + j3)) * 14
            + (d0 * 2 + k3)) * 192;
}
__device__ __forceinline__ float warp_sum(float v) {
#pragma unroll
    for (int o = 16; o; o >>= 1) v += __shfl_xor_sync(0xffffffffu, v, o);
    return v;
}
__device__ __forceinline__ uint32_t smem_u32(const void* p) {
    uint32_t a;
    asm("{ .reg .u64 t; cvta.to.shared.u64 t, %1; cvt.u32.u64 %0, t; }" : "=r"(a) : "l"(p));
    return a;
}
__device__ __forceinline__ void cp16(uint32_t dst, const void* src) {
    asm volatile("cp.async.cg.shared.global [%0], [%1], 16;" :: "r"(dst), "l"(src));
}
#define CP_COMMIT() asm volatile("cp.async.commit_group;" ::: "memory")
#define CP_WAIT(n)  asm volatile("cp.async.wait_group %0;" :: "n"(n) : "memory")

__device__ __forceinline__ void ldsm_x4(uint32_t* r, uint32_t a) {
    asm volatile("ldmatrix.sync.aligned.m8n8.x4.shared.b16 {%0,%1,%2,%3}, [%4];"
                 : "=r"(r[0]), "=r"(r[1]), "=r"(r[2]), "=r"(r[3]) : "r"(a));
}
__device__ __forceinline__ void mma_bf16(float* d, const uint32_t* a,
                                         const uint32_t* b, const float* c) {
    asm volatile(
        "mma.sync.aligned.m16n8k16.row.col.f32.bf16.bf16.f32 "
        "{%0,%1,%2,%3}, {%4,%5,%6,%7}, {%8,%9}, {%10,%11,%12,%13};"
        : "=f"(d[0]), "=f"(d[1]), "=f"(d[2]), "=f"(d[3])
        : "r"(a[0]), "r"(a[1]), "r"(a[2]), "r"(a[3]),
          "r"(b[0]), "r"(b[1]),
          "f"(c[0]), "f"(c[1]), "f"(c[2]), "f"(c[3]));
}
__device__ __forceinline__ float2 bf2f2(uint32_t u) {
    __nv_bfloat162 b = *reinterpret_cast<__nv_bfloat162*>(&u);
    return __bfloat1622float2(b);
}
__device__ __forceinline__ uint32_t f2bf2u(float lo, float hi) {
    __nv_bfloat162 b = __floats2bfloat162_rn(lo, hi);
    return *reinterpret_cast<uint32_t*>(&b);
}

// ---------------- one-shot weight transpose (all 4 weights) ----------------
__global__ void transpose_all_kernel(
    const float* __restrict__ qkv_w, const float* __restrict__ proj_w,
    const float* __restrict__ w1, const float* __restrict__ w2,
    bf16* __restrict__ qkv_wt, bf16* __restrict__ proj_wt,
    bf16* __restrict__ w1t, bf16* __restrict__ w2t)
{
    __shared__ float t[32][33];
    int bid = blockIdx.x;
    const float* W; bf16* Wt; int K, N, loc;
    if (bid < 108)      { W = qkv_w;  Wt = qkv_wt;  K = 192; N = 576; loc = bid; }
    else if (bid < 144) { W = proj_w; Wt = proj_wt; K = 192; N = 192; loc = bid - 108; }
    else if (bid < 288) { W = w1;     Wt = w1t;     K = 192; N = 768; loc = bid - 144; }
    else                { W = w2;     Wt = w2t;     K = 768; N = 192; loc = bid - 288; }
    int Kt = K / 32;
    int kb = (loc % Kt) * 32, nb = (loc / Kt) * 32;
    int x = threadIdx.x, y = threadIdx.y;
#pragma unroll
    for (int j = 0; j < 32; j += 8) t[y + j][x] = W[(size_t)(kb + y + j) * N + nb + x];
    __syncthreads();
#pragma unroll
    for (int j = 0; j < 32; j += 8)
        Wt[(size_t)(nb + y + j) * K + kb + x] = __float2bfloat16(t[x][y + j]);
}

// ---------------- bias precompute (TRANSPOSED): bias6[h*576 + m*24 + n] -----
__global__ void bias_precompute_kernel(const float* __restrict__ bias_table,
                                       const int* __restrict__ rel_index)
{
    int h = blockIdx.x, idx = threadIdx.x;   // idx = m*24 + n
    if (idx < 576) {
        int m = idx / 24, n = idx - m * 24;
        g_bias6[h * 576 + idx] = bias_table[rel_index[n * 24 + m] * HEADS + h];
    }
}

// ---------------- gather + LN1 ----------------
__global__ __launch_bounds__(256) void gather_ln1_kernel(
    const float* __restrict__ x, const float* __restrict__ gam, const float* __restrict__ bet)
{
    int t = blockIdx.x * 8 + (threadIdx.x >> 5);
    int lane = threadIdx.x & 31;
    size_t src = token_src_offset(t);
    float v[6]; float s = 0.f;
#pragma unroll
    for (int q = 0; q < 6; q++) { v[q] = x[src + lane + q * 32]; s += v[q]; }
    float mean = warp_sum(s) * (1.0f / 192.0f);
    float vs = 0.f;
#pragma unroll
    for (int q = 0; q < 6; q++) { float d = v[q] - mean; vs += d * d; }
    float rstd = rsqrtf(warp_sum(vs) * (1.0f / 192.0f) + 1e-5f);
    size_t dst = (size_t)t * 192;
#pragma unroll
    for (int q = 0; q < 6; q++) {
        int c = lane + q * 32;
        g_h[dst + c] = __float2bfloat16((v[q] - mean) * rstd * gam[c] + bet[c]);
    }
}

// ---------------- attention: lane = query row, shfl-free softmax ------------
__global__ __launch_bounds__(256) void attn_kernel()
{
    __shared__ float k_s[8][768];   // [m*32 + d]
    __shared__ float v_s[8][768];
    const int w = threadIdx.x >> 5, lane = threadIdx.x & 31;
    const int pair = blockIdx.x * 8 + w;
    const int h = pair % 6;
    const bf16* base = g_qkv + (size_t)pair * 2304;   // [q 768 | k 768 | v 768]
    const float* bias = g_bias6 + h * 576;            // [m][n]

#pragma unroll
    for (int j = 0; j < 3; j++) {
        int idx = (lane + j * 32) * 8;
        uint4 uk = *(const uint4*)(base + 768 + idx);
        uint4 uv = *(const uint4*)(base + 1536 + idx);
        float2 f;
        f = bf2f2(uk.x); k_s[w][idx+0] = f.x; k_s[w][idx+1] = f.y;
        f = bf2f2(uk.y); k_s[w][idx+2] = f.x; k_s[w][idx+3] = f.y;
        f = bf2f2(uk.z); k_s[w][idx+4] = f.x; k_s[w][idx+5] = f.y;
        f = bf2f2(uk.w); k_s[w][idx+6] = f.x; k_s[w][idx+7] = f.y;
        f = bf2f2(uv.x); v_s[w][idx+0] = f.x; v_s[w][idx+1] = f.y;
        f = bf2f2(uv.y); v_s[w][idx+2] = f.x; v_s[w][idx+3] = f.y;
        f = bf2f2(uv.z); v_s[w][idx+4] = f.x; v_s[w][idx+5] = f.y;
        f = bf2f2(uv.w); v_s[w][idx+6] = f.x; v_s[w][idx+7] = f.y;
    }
    __syncwarp();

    if (lane < 24) {
        float q[32];
        const bf16* qp = base + lane * 32;
#pragma unroll
        for (int d = 0; d < 32; d += 8) {
            uint4 u = *(const uint4*)(qp + d);
            float2 f;
            f = bf2f2(u.x); q[d+0] = f.x; q[d+1] = f.y;
            f = bf2f2(u.y); q[d+2] = f.x; q[d+3] = f.y;
            f = bf2f2(u.z); q[d+4] = f.x; q[d+5] = f.y;
            f = bf2f2(u.w); q[d+6] = f.x; q[d+7] = f.y;
        }

        const float scale = 0.17677669529663687f;  // 32^-0.5
        float p[24];
        float mx = -1e30f;
#pragma unroll 4
        for (int m = 0; m < 24; m++) {
            float a = 0.f;
#pragma unroll
            for (int d = 0; d < 32; d += 4) {
                float4 k4 = *(const float4*)&k_s[w][m * 32 + d];
                a = fmaf(q[d],   k4.x, a); a = fmaf(q[d+1], k4.y, a);
                a = fmaf(q[d+2], k4.z, a); a = fmaf(q[d+3], k4.w, a);
            }
            a = a * scale + bias[m * 24 + lane];
            p[m] = a;
            mx = fmaxf(mx, a);
        }
        float sm = 0.f;
#pragma unroll
        for (int m = 0; m < 24; m++) { p[m] = __expf(p[m] - mx); sm += p[m]; }
        float inv = 1.0f / sm;

        float o[32];
#pragma unroll
        for (int d = 0; d < 32; d++) o[d] = 0.f;
#pragma unroll 4
        for (int m = 0; m < 24; m++) {
            float pm = p[m];
#pragma unroll
            for (int d = 0; d < 32; d += 4) {
                float4 v4 = *(const float4*)&v_s[w][m * 32 + d];
                o[d]   = fmaf(pm, v4.x, o[d]);
                o[d+1] = fmaf(pm, v4.y, o[d+1]);
                o[d+2] = fmaf(pm, v4.z, o[d+2]);
                o[d+3] = fmaf(pm, v4.w, o[d+3]);
            }
        }
        bf16* ob = g_attn + (size_t)pair * 768 + lane * 32;
#pragma unroll
        for (int d = 0; d < 32; d += 8) {
            uint4 u;
            u.x = f2bf2u(o[d]*inv,   o[d+1]*inv);
            u.y = f2bf2u(o[d+2]*inv, o[d+3]*inv);
            u.z = f2bf2u(o[d+4]*inv, o[d+5]*inv);
            u.w = f2bf2u(o[d+6]*inv, o[d+7]*inv);
            *(uint4*)(ob + d) = u;
        }
    }
}

// ======================= generic bf16 GEMM (BN=96) ==========================
// 3-stage cp.async pipeline (R10 config) + hoisted ldsm/cp.async addressing.
// EPI: 0 bias->bf16 scatter to qkv layout, 1 bias+gelu->bf16,
//      3 bias+res+scatter->fp32 output
#define GEMM_SMEM (3 * (128 + 96) * 40 * 2)
template <int EPI>
__global__ __launch_bounds__(256, 3) void tc_gemm(
    const bf16* __restrict__ A, const bf16* __restrict__ Bt,
    const float* __restrict__ bias, const float* __restrict__ res,
    void* __restrict__ Cc, int N, int K)
{
    constexpr int LDA = 40;
    constexpr int ASZ = 128 * LDA, BSZ = 96 * LDA;   // halves per buffer
    extern __shared__ bf16 smem[];
    bf16* Asb = smem;
    bf16* Bsb = smem + 3 * ASZ;

    const int tid  = threadIdx.x;
    const int lane = tid & 31;
    const int wid  = tid >> 5;
    const int wm   = wid & 3;
    const int wn   = wid >> 2;
    const int col0 = blockIdx.x * 96;
    const int row0 = blockIdx.y * 128;
    const int gq = lane >> 2, tg = lane & 3;

    const uint32_t sAb = smem_u32(Asb), sBb = smem_u32(Bsb);
    // hoisted ldsm bases (byte offsets within a buffer)
    const uint32_t a_rel = (uint32_t)(((wm * 32 + (lane & 15)) * LDA
                                       + (lane >> 4) * 8) * 2);
    uint32_t b_rel[3];
#pragma unroll
    for (int p = 0; p < 3; p++)
        b_rel[p] = (uint32_t)(((wn * 48 + p * 16 + (lane & 7) + ((lane >> 4) << 3)) * LDA
                              + ((lane >> 3) & 1) * 8) * 2);
    // hoisted cp.async dest offsets and per-thread source row/col
    const int cr0 = tid >> 2, cr1 = (tid + 256) >> 2, cc = (tid & 3);
    const uint32_t cpa0 = (uint32_t)(cr0 * 80 + cc * 16);
    const uint32_t cpa1 = (uint32_t)(cr1 * 80 + cc * 16);

    float acc[2][6][4];
#pragma unroll
    for (int mi = 0; mi < 2; mi++)
#pragma unroll
        for (int ni = 0; ni < 6; ni++)
#pragma unroll
            for (int j = 0; j < 4; j++) acc[mi][ni][j] = 0.f;

    const int nstages = K / 32;

    auto prefetch = [&](int s, int b) {
        const bf16* Ag = A + (size_t)row0 * K + s * 32 + cc * 8;
        const bf16* Bg = Bt + (size_t)col0 * K + s * 32 + cc * 8;
        uint32_t sA = sAb + (uint32_t)b * (ASZ * 2);
        uint32_t sB = sBb + (uint32_t)b * (BSZ * 2);
        cp16(sA + cpa0, Ag + (size_t)cr0 * K);
        cp16(sA + cpa1, Ag + (size_t)cr1 * K);
        cp16(sB + cpa0, Bg + (size_t)cr0 * K);
        if (tid < 128)
            cp16(sB + cpa1, Bg + (size_t)cr1 * K);
        CP_COMMIT();
    };

    prefetch(0, 0);
    prefetch(1, 1);

    for (int s = 0; s < nstages; s++) {
        if (s < nstages - 1) CP_WAIT(1); else CP_WAIT(0);
        __syncthreads();
        if (s + 2 < nstages) prefetch(s + 2, (s + 2) % 3);

        const int b = s % 3;
        const uint32_t sA = sAb + (uint32_t)b * (ASZ * 2) + a_rel;
        const uint32_t sBB = sBb + (uint32_t)b * (BSZ * 2);
#pragma unroll
        for (int kk = 0; kk < 32; kk += 16) {
            uint32_t afr[2][4];
#pragma unroll
            for (int mi = 0; mi < 2; mi++)
                ldsm_x4(afr[mi], sA + (uint32_t)(kk * 2 + mi * (16 * LDA * 2)));

            uint32_t bfr[6][2];
#pragma unroll
            for (int p = 0; p < 3; p++) {
                uint32_t r4[4];
                ldsm_x4(r4, sBB + b_rel[p] + (uint32_t)(kk * 2));
                bfr[2*p][0] = r4[0]; bfr[2*p][1] = r4[1];
                bfr[2*p+1][0] = r4[2]; bfr[2*p+1][1] = r4[3];
            }
#pragma unroll
            for (int mi = 0; mi < 2; mi++)
#pragma unroll
                for (int ni = 0; ni < 6; ni++)
                    mma_bf16(acc[mi][ni], afr[mi], bfr[ni], acc[mi][ni]);
        }
        __syncthreads();
    }

#pragma unroll
    for (int mi = 0; mi < 2; mi++) {
#pragma unroll
        for (int ni = 0; ni < 6; ni++) {
            int row = row0 + wm * 32 + mi * 16 + gq;
            int col = col0 + wn * 48 + ni * 8 + tg * 2;
            float b0 = bias[col], b1 = bias[col + 1];
#pragma unroll
            for (int hh = 0; hh < 2; hh++) {
                int r = row + hh * 8;
                float v0 = acc[mi][ni][hh * 2]     + b0;
                float v1 = acc[mi][ni][hh * 2 + 1] + b1;
                if (EPI == 1) {
                    v0 = 0.5f * v0 * (1.0f + erff(v0 * 0.70710678118654752f));
                    v1 = 0.5f * v1 * (1.0f + erff(v1 * 0.70710678118654752f));
                }
                if (EPI == 0) {
                    int wi2 = r / 24, n2 = r - wi2 * 24;
                    int which = col / 192;
                    int rem = col - which * 192;
                    int h2 = rem >> 5, d2 = rem & 31;
                    bf16* cp_ = (bf16*)Cc +
                        ((((size_t)wi2 * 6 + h2) * 3 + which) * 768 + n2 * 32 + d2);
                    *(__nv_bfloat162*)cp_ = __floats2bfloat162_rn(v0, v1);
                } else if (EPI == 3) {
                    const float* rp = res + (size_t)r * 192 + col;
                    v0 += rp[0]; v1 += rp[1];
                    size_t off = token_src_offset(r) + col;
                    *(float2*)((float*)Cc + off) = make_float2(v0, v1);
                } else {
                    bf16* cp_ = (bf16*)Cc + (size_t)r * N + col;
                    *(__nv_bfloat162*)cp_ = __floats2bfloat162_rn(v0, v1);
                }
            }
        }
    }
}

// ===== proj GEMM (BM=64, BN=192) + residual(from x) + LN2, 3 CTAs/SM ========
#define PROJ_SMEM (3 * (64 + 192) * 40 * 2)
__global__ __launch_bounds__(256, 3) void proj_ln2_kernel(
    const bf16* __restrict__ A, const bf16* __restrict__ Bt,
    const float* __restrict__ bias, const float* __restrict__ x,
    const float* __restrict__ gam, const float* __restrict__ bet)
{
    constexpr int LDA = 40, K = 192;
    constexpr int ASZ = 64 * LDA, BSZ = 192 * LDA;
    extern __shared__ bf16 smem[];
    bf16* Asb = smem;
    bf16* Bsb = smem + 3 * ASZ;
    __shared__ float s_sum[64][4];
    __shared__ float s_sq [64][4];

    const int tid  = threadIdx.x;
    const int lane = tid & 31;
    const int wid  = tid >> 5;
    const int wm   = wid & 1;
    const int wn   = wid >> 1;
    const int row0 = blockIdx.x * 64;
    const int gq = lane >> 2, tg = lane & 3;

    const uint32_t sAb = smem_u32(Asb), sBb = smem_u32(Bsb);
    const uint32_t a_rel = (uint32_t)(((wm * 32 + (lane & 15)) * LDA
                                       + (lane >> 4) * 8) * 2);
    uint32_t b_rel[3];
#pragma unroll
    for (int p = 0; p < 3; p++)
        b_rel[p] = (uint32_t)(((wn * 48 + p * 16 + (lane & 7) + ((lane >> 4) << 3)) * LDA
                              + ((lane >> 3) & 1) * 8) * 2);

    float acc[2][6][4];
#pragma unroll
    for (int mi = 0; mi < 2; mi++)
#pragma unroll
        for (int ni = 0; ni < 6; ni++)
#pragma unroll
            for (int j = 0; j < 4; j++) acc[mi][ni][j] = 0.f;

    const int nstages = 6;

    auto prefetch = [&](int s, int b) {
        const bf16* Bg = Bt + (size_t)s * 32;
        uint32_t sA = sAb + (uint32_t)b * (ASZ * 2);
        uint32_t sB = sBb + (uint32_t)b * (BSZ * 2);
        {
            int r = tid >> 2, c4 = tid & 3;
            int rg = row0 + r;
            int win = rg / 24, n2 = rg - win * 24;
            const bf16* src = A + ((size_t)win * 6 + s) * 768 + n2 * 32 + c4 * 8;
            cp16(sA + (uint32_t)(r * 80 + c4 * 16), src);
        }
#pragma unroll
        for (int j = 0; j < 3; j++) {
            int idx = tid + j * 256;
            int r = idx >> 2, c = idx & 3;
            cp16(sB + (uint32_t)(r * 80 + c * 16), Bg + (size_t)r * K + c * 8);
        }
        CP_COMMIT();
    };

    prefetch(0, 0);
    prefetch(1, 1);

    for (int s = 0; s < nstages; s++) {
        if (s < nstages - 1) CP_WAIT(1); else CP_WAIT(0);
        __syncthreads();
        if (s + 2 < nstages) prefetch(s + 2, (s + 2) % 3);

        const int b = s % 3;
        const uint32_t sA = sAb + (uint32_t)b * (ASZ * 2) + a_rel;
        const uint32_t sBB = sBb + (uint32_t)b * (BSZ * 2);
#pragma unroll
        for (int kk = 0; kk < 32; kk += 16) {
            uint32_t afr[2][4];
#pragma unroll
            for (int mi = 0; mi < 2; mi++)
                ldsm_x4(afr[mi], sA + (uint32_t)(kk * 2 + mi * (16 * LDA * 2)));

            uint32_t bfr[6][2];
#pragma unroll
            for (int p = 0; p < 3; p++) {
                uint32_t r4[4];
                ldsm_x4(r4, sBB + b_rel[p] + (uint32_t)(kk * 2));
                bfr[2*p][0] = r4[0]; bfr[2*p][1] = r4[1];
                bfr[2*p+1][0] = r4[2]; bfr[2*p+1][1] = r4[3];
            }
#pragma unroll
            for (int mi = 0; mi < 2; mi++)
#pragma unroll
                for (int ni = 0; ni < 6; ni++)
                    mma_bf16(acc[mi][ni], afr[mi], bfr[ni], acc[mi][ni]);
        }
        __syncthreads();
    }

    // ---- epilogue: bias + residual(from x) + row stats ----
#pragma unroll
    for (int mi = 0; mi < 2; mi++) {
#pragma unroll
        for (int hh = 0; hh < 2; hh++) {
            int rl = wm * 32 + mi * 16 + gq + hh * 8;
            int r  = row0 + rl;
            size_t roff = token_src_offset(r);
            float s1 = 0.f, s2 = 0.f;
#pragma unroll
            for (int ni = 0; ni < 6; ni++) {
                int col = wn * 48 + ni * 8 + tg * 2;
                float2 rx = *(const float2*)(x + roff + col);
                float v0 = acc[mi][ni][hh*2]     + bias[col]     + rx.x;
                float v1 = acc[mi][ni][hh*2 + 1] + bias[col + 1] + rx.y;
                acc[mi][ni][hh*2]     = v0;
                acc[mi][ni][hh*2 + 1] = v1;
                s1 += v0 + v1;
                s2 += v0 * v0 + v1 * v1;
            }
            s1 += __shfl_xor_sync(0xffffffffu, s1, 1);
            s1 += __shfl_xor_sync(0xffffffffu, s1, 2);
            s2 += __shfl_xor_sync(0xffffffffu, s2, 1);
            s2 += __shfl_xor_sync(0xffffffffu, s2, 2);
            if (tg == 0) { s_sum[rl][wn] = s1; s_sq[rl][wn] = s2; }
        }
    }
    __syncthreads();
#pragma unroll
    for (int mi = 0; mi < 2; mi++) {
#pragma unroll
        for (int hh = 0; hh < 2; hh++) {
            int rl = wm * 32 + mi * 16 + gq + hh * 8;
            int r  = row0 + rl;
            float S1 = s_sum[rl][0] + s_sum[rl][1] + s_sum[rl][2] + s_sum[rl][3];
            float S2 = s_sq [rl][0] + s_sq [rl][1] + s_sq [rl][2] + s_sq [rl][3];
            float mean = S1 * (1.0f / 192.0f);
            float var  = S2 * (1.0f / 192.0f) - mean * mean;
            float rstd = rsqrtf(var + 1e-5f);
#pragma unroll
            for (int ni = 0; ni < 6; ni++) {
                int col = wn * 48 + ni * 8 + tg * 2;
                float v0 = acc[mi][ni][hh*2], v1 = acc[mi][ni][hh*2 + 1];
                *(float2*)(g_x2 + (size_t)r * 192 + col) = make_float2(v0, v1);
                float n0 = (v0 - mean) * rstd * gam[col]     + bet[col];
                float n1 = (v1 - mean) * rstd * gam[col + 1] + bet[col + 1];
                *(__nv_bfloat162*)(g_h + (size_t)r * 192 + col) =
                    __floats2bfloat162_rn(n0, n1);
            }
        }
    }
}

// ---------------- host launcher ----------------
extern "C" void kernel_launch(void* const* d_in, const int* in_sizes, int n_in,
                              void* d_out, int out_size)
{
    const float* x      = (const float*)d_in[0];
    const float* ln1_g  = (const float*)d_in[1];
    const float* ln1_b  = (const float*)d_in[2];
    const float* qkv_w  = (const float*)d_in[3];
    const float* qkv_b  = (const float*)d_in[4];
    const float* btab   = (const float*)d_in[5];
    const float* proj_w = (const float*)d_in[6];
    const float* proj_b = (const float*)d_in[7];
    const float* ln2_g  = (const float*)d_in[8];
    const float* ln2_b  = (const float*)d_in[9];
    const float* mlp_w1 = (const float*)d_in[10];
    const float* mlp_b1 = (const float*)d_in[11];
    const float* mlp_w2 = (const float*)d_in[12];
    const float* mlp_b2 = (const float*)d_in[13];
    const int*   rel_idx= (const int*)d_in[14];
    float*       out    = (float*)d_out;

    bf16 *p_h, *p_qkv, *p_attn, *p_hid;
    float *p_x2;
    bf16 *p_qkv_wt, *p_proj_wt, *p_w1t, *p_w2t;
    cudaGetSymbolAddress((void**)&p_h,    g_h);
    cudaGetSymbolAddress((void**)&p_qkv,  g_qkv);
    cudaGetSymbolAddress((void**)&p_attn, g_attn);
    cudaGetSymbolAddress((void**)&p_x2,   g_x2);
    cudaGetSymbolAddress((void**)&p_hid,  g_hid);
    cudaGetSymbolAddress((void**)&p_qkv_wt,  g_qkv_wt);
    cudaGetSymbolAddress((void**)&p_proj_wt, g_proj_wt);
    cudaGetSymbolAddress((void**)&p_w1t,  g_w1t);
    cudaGetSymbolAddress((void**)&p_w2t,  g_w2t);

    cudaFuncSetAttribute(tc_gemm<0>, cudaFuncAttributeMaxDynamicSharedMemorySize, GEMM_SMEM);
    cudaFuncSetAttribute(tc_gemm<1>, cudaFuncAttributeMaxDynamicSharedMemorySize, GEMM_SMEM);
    cudaFuncSetAttribute(tc_gemm<3>, cudaFuncAttributeMaxDynamicSharedMemorySize, GEMM_SMEM);
    cudaFuncSetAttribute(proj_ln2_kernel, cudaFuncAttributeMaxDynamicSharedMemorySize, PROJ_SMEM);

    transpose_all_kernel<<<432, dim3(32, 8)>>>(qkv_w, proj_w, mlp_w1, mlp_w2,
                                               p_qkv_wt, p_proj_wt, p_w1t, p_w2t);
    bias_precompute_kernel<<<HEADS, 576>>>(btab, rel_idx);

    gather_ln1_kernel<<<NTOK_TOTAL / 8, 256>>>(x, ln1_g, ln1_b);

    const int Mb = NTOK_TOTAL / 128;  // 1008
    tc_gemm<0><<<dim3(6, Mb), 256, GEMM_SMEM>>>(p_h, p_qkv_wt, qkv_b, nullptr, p_qkv, 576, 192);
    attn_kernel<<<NWIN * HEADS / 8, 256>>>();
    proj_ln2_kernel<<<NTOK_TOTAL / 64, 256, PROJ_SMEM>>>(p_attn, p_proj_wt, proj_b, x, ln2_g, ln2_b);
    tc_gemm<1><<<dim3(8, Mb), 256, GEMM_SMEM>>>(p_h, p_w1t, mlp_b1, nullptr, p_hid, 768, 192);
    tc_gemm<3><<<dim3(2, Mb), 256, GEMM_SMEM>>>(p_hid, p_w2t, mlp_b2, p_x2, out, 192, 768);
}

// round 13
// speedup vs baseline: 1.0217x; 1.0100x over previous
#include <cuda_runtime.h>
#include <cuda_bf16.h>
#include <math.h>
#include <stdint.h>

typedef __nv_bfloat16 bf16;

// ---------------- problem constants ----------------
#define NTOK_TOTAL 129024   // 5376 windows * 24 tokens
#define NWIN       5376
#define HEADS      6

// ---------------- scratch (device globals) ----------------
__device__ float g_x2  [(size_t)NTOK_TOTAL * 192];   // trunk after proj (fp32)
__device__ bf16  g_h   [(size_t)NTOK_TOTAL * 192];   // LN out (bf16, GEMM A)
// qkv in attention-native layout: [win][head][q|k|v][24][32]
__device__ bf16  g_qkv [(size_t)NTOK_TOTAL * 576];
// attn out in [win][head][24][32] layout
__device__ bf16  g_attn[(size_t)NTOK_TOTAL * 192];
__device__ bf16  g_hid [(size_t)NTOK_TOTAL * 768];
__device__ float g_bias6[HEADS * 576];               // bias[h][m][n] (transposed!)
// pre-transposed bf16 weights (K-major: Wt[N][K])
__device__ bf16 g_qkv_wt [576 * 192];
__device__ bf16 g_proj_wt[192 * 192];
__device__ bf16 g_w1t    [768 * 192];
__device__ bf16 g_w2t    [192 * 768];

// ---------------- helpers ----------------
__device__ __forceinline__ size_t token_src_offset(int t) {
    int wi = t / 24, n = t % 24;
    int i3 = n / 12, j3 = (n >> 1) % 6, k3 = n & 1;
    int d0 = wi % 7;  int r = wi / 7;
    int w0 = r % 16;  r /= 16;
    int h0 = r % 24;  int b0 = r / 24;
    return ((((size_t)b0 * 48 + (h0 * 2 + i3)) * 96 + (w0 * 6 + j3)) * 14
            + (d0 * 2 + k3)) * 192;
}
__device__ __forceinline__ float warp_sum(float v) {
#pragma unroll
    for (int o = 16; o; o >>= 1) v += __shfl_xor_sync(0xffffffffu, v, o);
    return v;
}
__device__ __forceinline__ uint32_t smem_u32(const void* p) {
    uint32_t a;
    asm("{ .reg .u64 t; cvta.to.shared.u64 t, %1; cvt.u32.u64 %0, t; }" : "=r"(a) : "l"(p));
    return a;
}
__device__ __forceinline__ void cp16(uint32_t dst, const void* src) {
    asm volatile("cp.async.cg.shared.global [%0], [%1], 16;" :: "r"(dst), "l"(src));
}
#define CP_COMMIT() asm volatile("cp.async.commit_group;" ::: "memory")
#define CP_WAIT(n)  asm volatile("cp.async.wait_group %0;" :: "n"(n) : "memory")

__device__ __forceinline__ void ldsm_x4(uint32_t* r, uint32_t a) {
    asm volatile("ldmatrix.sync.aligned.m8n8.x4.shared.b16 {%0,%1,%2,%3}, [%4];"
                 : "=r"(r[0]), "=r"(r[1]), "=r"(r[2]), "=r"(r[3]) : "r"(a));
}
__device__ __forceinline__ void mma_bf16(float* d, const uint32_t* a,
                                         const uint32_t* b, const float* c) {
    asm volatile(
        "mma.sync.aligned.m16n8k16.row.col.f32.bf16.bf16.f32 "
        "{%0,%1,%2,%3}, {%4,%5,%6,%7}, {%8,%9}, {%10,%11,%12,%13};"
        : "=f"(d[0]), "=f"(d[1]), "=f"(d[2]), "=f"(d[3])
        : "r"(a[0]), "r"(a[1]), "r"(a[2]), "r"(a[3]),
          "r"(b[0]), "r"(b[1]),
          "f"(c[0]), "f"(c[1]), "f"(c[2]), "f"(c[3]));
}
__device__ __forceinline__ float2 bf2f2(uint32_t u) {
    __nv_bfloat162 b = *reinterpret_cast<__nv_bfloat162*>(&u);
    return __bfloat1622float2(b);
}
__device__ __forceinline__ uint32_t f2bf2u(float lo, float hi) {
    __nv_bfloat162 b = __floats2bfloat162_rn(lo, hi);
    return *reinterpret_cast<uint32_t*>(&b);
}

// ---------------- one-shot weight transpose (all 4 weights) ----------------
__global__ void transpose_all_kernel(
    const float* __restrict__ qkv_w, const float* __restrict__ proj_w,
    const float* __restrict__ w1, const float* __restrict__ w2,
    bf16* __restrict__ qkv_wt, bf16* __restrict__ proj_wt,
    bf16* __restrict__ w1t, bf16* __restrict__ w2t)
{
    __shared__ float t[32][33];
    int bid = blockIdx.x;
    const float* W; bf16* Wt; int K, N, loc;
    if (bid < 108)      { W = qkv_w;  Wt = qkv_wt;  K = 192; N = 576; loc = bid; }
    else if (bid < 144) { W = proj_w; Wt = proj_wt; K = 192; N = 192; loc = bid - 108; }
    else if (bid < 288) { W = w1;     Wt = w1t;     K = 192; N = 768; loc = bid - 144; }
    else                { W = w2;     Wt = w2t;     K = 768; N = 192; loc = bid - 288; }
    int Kt = K / 32;
    int kb = (loc % Kt) * 32, nb = (loc / Kt) * 32;
    int x = threadIdx.x, y = threadIdx.y;
#pragma unroll
    for (int j = 0; j < 32; j += 8) t[y + j][x] = W[(size_t)(kb + y + j) * N + nb + x];
    __syncthreads();
#pragma unroll
    for (int j = 0; j < 32; j += 8)
        Wt[(size_t)(nb + y + j) * K + kb + x] = __float2bfloat16(t[x][y + j]);
}

// ---------------- bias precompute (TRANSPOSED): bias6[h*576 + m*24 + n] -----
__global__ void bias_precompute_kernel(const float* __restrict__ bias_table,
                                       const int* __restrict__ rel_index)
{
    int h = blockIdx.x, idx = threadIdx.x;   // idx = m*24 + n
    if (idx < 576) {
        int m = idx / 24, n = idx - m * 24;
        g_bias6[h * 576 + idx] = bias_table[rel_index[n * 24 + m] * HEADS + h];
    }
}

// ---------------- gather + LN1 ----------------
__global__ __launch_bounds__(256) void gather_ln1_kernel(
    const float* __restrict__ x, const float* __restrict__ gam, const float* __restrict__ bet)
{
    int t = blockIdx.x * 8 + (threadIdx.x >> 5);
    int lane = threadIdx.x & 31;
    size_t src = token_src_offset(t);
    float v[6]; float s = 0.f;
#pragma unroll
    for (int q = 0; q < 6; q++) { v[q] = x[src + lane + q * 32]; s += v[q]; }
    float mean = warp_sum(s) * (1.0f / 192.0f);
    float vs = 0.f;
#pragma unroll
    for (int q = 0; q < 6; q++) { float d = v[q] - mean; vs += d * d; }
    float rstd = rsqrtf(warp_sum(vs) * (1.0f / 192.0f) + 1e-5f);
    size_t dst = (size_t)t * 192;
#pragma unroll
    for (int q = 0; q < 6; q++) {
        int c = lane + q * 32;
        g_h[dst + c] = __float2bfloat16((v[q] - mean) * rstd * gam[c] + bet[c]);
    }
}

// ---------------- attention: lane = query row, shfl-free softmax ------------
__global__ __launch_bounds__(256) void attn_kernel()
{
    __shared__ float k_s[8][768];   // [m*32 + d]
    __shared__ float v_s[8][768];
    const int w = threadIdx.x >> 5, lane = threadIdx.x & 31;
    const int pair = blockIdx.x * 8 + w;
    const int h = pair % 6;
    const bf16* base = g_qkv + (size_t)pair * 2304;   // [q 768 | k 768 | v 768]
    const float* bias = g_bias6 + h * 576;            // [m][n]

#pragma unroll
    for (int j = 0; j < 3; j++) {
        int idx = (lane + j * 32) * 8;
        uint4 uk = *(const uint4*)(base + 768 + idx);
        uint4 uv = *(const uint4*)(base + 1536 + idx);
        float2 f;
        f = bf2f2(uk.x); k_s[w][idx+0] = f.x; k_s[w][idx+1] = f.y;
        f = bf2f2(uk.y); k_s[w][idx+2] = f.x; k_s[w][idx+3] = f.y;
        f = bf2f2(uk.z); k_s[w][idx+4] = f.x; k_s[w][idx+5] = f.y;
        f = bf2f2(uk.w); k_s[w][idx+6] = f.x; k_s[w][idx+7] = f.y;
        f = bf2f2(uv.x); v_s[w][idx+0] = f.x; v_s[w][idx+1] = f.y;
        f = bf2f2(uv.y); v_s[w][idx+2] = f.x; v_s[w][idx+3] = f.y;
        f = bf2f2(uv.z); v_s[w][idx+4] = f.x; v_s[w][idx+5] = f.y;
        f = bf2f2(uv.w); v_s[w][idx+6] = f.x; v_s[w][idx+7] = f.y;
    }
    __syncwarp();

    if (lane < 24) {
        float q[32];
        const bf16* qp = base + lane * 32;
#pragma unroll
        for (int d = 0; d < 32; d += 8) {
            uint4 u = *(const uint4*)(qp + d);
            float2 f;
            f = bf2f2(u.x); q[d+0] = f.x; q[d+1] = f.y;
            f = bf2f2(u.y); q[d+2] = f.x; q[d+3] = f.y;
            f = bf2f2(u.z); q[d+4] = f.x; q[d+5] = f.y;
            f = bf2f2(u.w); q[d+6] = f.x; q[d+7] = f.y;
        }

        const float scale = 0.17677669529663687f;  // 32^-0.5
        float p[24];
        float mx = -1e30f;
#pragma unroll 4
        for (int m = 0; m < 24; m++) {
            float a = 0.f;
#pragma unroll
            for (int d = 0; d < 32; d += 4) {
                float4 k4 = *(const float4*)&k_s[w][m * 32 + d];
                a = fmaf(q[d],   k4.x, a); a = fmaf(q[d+1], k4.y, a);
                a = fmaf(q[d+2], k4.z, a); a = fmaf(q[d+3], k4.w, a);
            }
            a = a * scale + bias[m * 24 + lane];
            p[m] = a;
            mx = fmaxf(mx, a);
        }
        float sm = 0.f;
#pragma unroll
        for (int m = 0; m < 24; m++) { p[m] = __expf(p[m] - mx); sm += p[m]; }
        float inv = 1.0f / sm;

        float o[32];
#pragma unroll
        for (int d = 0; d < 32; d++) o[d] = 0.f;
#pragma unroll 4
        for (int m = 0; m < 24; m++) {
            float pm = p[m];
#pragma unroll
            for (int d = 0; d < 32; d += 4) {
                float4 v4 = *(const float4*)&v_s[w][m * 32 + d];
                o[d]   = fmaf(pm, v4.x, o[d]);
                o[d+1] = fmaf(pm, v4.y, o[d+1]);
                o[d+2] = fmaf(pm, v4.z, o[d+2]);
                o[d+3] = fmaf(pm, v4.w, o[d+3]);
            }
        }
        bf16* ob = g_attn + (size_t)pair * 768 + lane * 32;
#pragma unroll
        for (int d = 0; d < 32; d += 8) {
            uint4 u;
            u.x = f2bf2u(o[d]*inv,   o[d+1]*inv);
            u.y = f2bf2u(o[d+2]*inv, o[d+3]*inv);
            u.z = f2bf2u(o[d+4]*inv, o[d+5]*inv);
            u.w = f2bf2u(o[d+6]*inv, o[d+7]*inv);
            *(uint4*)(ob + d) = u;
        }
    }
}

// ======================= generic bf16 GEMM (BN=96) ==========================
// 3-stage cp.async pipeline, ONE barrier per stage, hoisted addressing.
// EPI: 0 bias->bf16 scatter to qkv layout, 1 bias+gelu->bf16,
//      3 bias+res+scatter->fp32 output
#define GEMM_SMEM (3 * (128 + 96) * 40 * 2)
template <int EPI>
__global__ __launch_bounds__(256, 3) void tc_gemm(
    const bf16* __restrict__ A, const bf16* __restrict__ Bt,
    const float* __restrict__ bias, const float* __restrict__ res,
    void* __restrict__ Cc, int N, int K)
{
    constexpr int LDA = 40;
    constexpr int ASZ = 128 * LDA, BSZ = 96 * LDA;   // halves per buffer
    extern __shared__ bf16 smem[];
    bf16* Asb = smem;
    bf16* Bsb = smem + 3 * ASZ;

    const int tid  = threadIdx.x;
    const int lane = tid & 31;
    const int wid  = tid >> 5;
    const int wm   = wid & 3;
    const int wn   = wid >> 2;
    const int col0 = blockIdx.x * 96;
    const int row0 = blockIdx.y * 128;
    const int gq = lane >> 2, tg = lane & 3;

    const uint32_t sAb = smem_u32(Asb), sBb = smem_u32(Bsb);
    const uint32_t a_rel = (uint32_t)(((wm * 32 + (lane & 15)) * LDA
                                       + (lane >> 4) * 8) * 2);
    uint32_t b_rel[3];
#pragma unroll
    for (int p = 0; p < 3; p++)
        b_rel[p] = (uint32_t)(((wn * 48 + p * 16 + (lane & 7) + ((lane >> 4) << 3)) * LDA
                              + ((lane >> 3) & 1) * 8) * 2);
    const int cr0 = tid >> 2, cr1 = (tid + 256) >> 2, cc = (tid & 3);
    const uint32_t cpa0 = (uint32_t)(cr0 * 80 + cc * 16);
    const uint32_t cpa1 = (uint32_t)(cr1 * 80 + cc * 16);

    float acc[2][6][4];
#pragma unroll
    for (int mi = 0; mi < 2; mi++)
#pragma unroll
        for (int ni = 0; ni < 6; ni++)
#pragma unroll
            for (int j = 0; j < 4; j++) acc[mi][ni][j] = 0.f;

    const int nstages = K / 32;

    auto prefetch = [&](int s, int b) {
        const bf16* Ag = A + (size_t)row0 * K + s * 32 + cc * 8;
        const bf16* Bg = Bt + (size_t)col0 * K + s * 32 + cc * 8;
        uint32_t sA = sAb + (uint32_t)b * (ASZ * 2);
        uint32_t sB = sBb + (uint32_t)b * (BSZ * 2);
        cp16(sA + cpa0, Ag + (size_t)cr0 * K);
        cp16(sA + cpa1, Ag + (size_t)cr1 * K);
        cp16(sB + cpa0, Bg + (size_t)cr0 * K);
        if (tid < 128)
            cp16(sB + cpa1, Bg + (size_t)cr1 * K);
        CP_COMMIT();
    };

    prefetch(0, 0);
    prefetch(1, 1);

    for (int s = 0; s < nstages; s++) {
        if (s < nstages - 1) CP_WAIT(1); else CP_WAIT(0);
        __syncthreads();
        if (s + 2 < nstages) prefetch(s + 2, (s + 2) % 3);

        const int b = s % 3;
        const uint32_t sA = sAb + (uint32_t)b * (ASZ * 2) + a_rel;
        const uint32_t sBB = sBb + (uint32_t)b * (BSZ * 2);
#pragma unroll
        for (int kk = 0; kk < 32; kk += 16) {
            uint32_t afr[2][4];
#pragma unroll
            for (int mi = 0; mi < 2; mi++)
                ldsm_x4(afr[mi], sA + (uint32_t)(kk * 2 + mi * (16 * LDA * 2)));

            uint32_t bfr[6][2];
#pragma unroll
            for (int p = 0; p < 3; p++) {
                uint32_t r4[4];
                ldsm_x4(r4, sBB + b_rel[p] + (uint32_t)(kk * 2));
                bfr[2*p][0] = r4[0]; bfr[2*p][1] = r4[1];
                bfr[2*p+1][0] = r4[2]; bfr[2*p+1][1] = r4[3];
            }
#pragma unroll
            for (int mi = 0; mi < 2; mi++)
#pragma unroll
                for (int ni = 0; ni < 6; ni++)
                    mma_bf16(acc[mi][ni], afr[mi], bfr[ni], acc[mi][ni]);
        }
    }

#pragma unroll
    for (int mi = 0; mi < 2; mi++) {
#pragma unroll
        for (int ni = 0; ni < 6; ni++) {
            int row = row0 + wm * 32 + mi * 16 + gq;
            int col = col0 + wn * 48 + ni * 8 + tg * 2;
            float b0 = bias[col], b1 = bias[col + 1];
#pragma unroll
            for (int hh = 0; hh < 2; hh++) {
                int r = row + hh * 8;
                float v0 = acc[mi][ni][hh * 2]     + b0;
                float v1 = acc[mi][ni][hh * 2 + 1] + b1;
                if (EPI == 1) {
                    v0 = 0.5f * v0 * (1.0f + erff(v0 * 0.70710678118654752f));
                    v1 = 0.5f * v1 * (1.0f + erff(v1 * 0.70710678118654752f));
                }
                if (EPI == 0) {
                    int wi2 = r / 24, n2 = r - wi2 * 24;
                    int which = col / 192;
                    int rem = col - which * 192;
                    int h2 = rem >> 5, d2 = rem & 31;
                    bf16* cp_ = (bf16*)Cc +
                        ((((size_t)wi2 * 6 + h2) * 3 + which) * 768 + n2 * 32 + d2);
                    *(__nv_bfloat162*)cp_ = __floats2bfloat162_rn(v0, v1);
                } else if (EPI == 3) {
                    const float* rp = res + (size_t)r * 192 + col;
                    v0 += rp[0]; v1 += rp[1];
                    size_t off = token_src_offset(r) + col;
                    *(float2*)((float*)Cc + off) = make_float2(v0, v1);
                } else {
                    bf16* cp_ = (bf16*)Cc + (size_t)r * N + col;
                    *(__nv_bfloat162*)cp_ = __floats2bfloat162_rn(v0, v1);
                }
            }
        }
    }
}

// ===== proj GEMM (BM=64, BN=192) + residual(from x) + LN2, 3 CTAs/SM ========
#define PROJ_SMEM (3 * (64 + 192) * 40 * 2)
__global__ __launch_bounds__(256, 3) void proj_ln2_kernel(
    const bf16* __restrict__ A, const bf16* __restrict__ Bt,
    const float* __restrict__ bias, const float* __restrict__ x,
    const float* __restrict__ gam, const float* __restrict__ bet)
{
    constexpr int LDA = 40, K = 192;
    constexpr int ASZ = 64 * LDA, BSZ = 192 * LDA;
    extern __shared__ bf16 smem[];
    bf16* Asb = smem;
    bf16* Bsb = smem + 3 * ASZ;
    __shared__ float s_sum[64][4];
    __shared__ float s_sq [64][4];

    const int tid  = threadIdx.x;
    const int lane = tid & 31;
    const int wid  = tid >> 5;
    const int wm   = wid & 1;
    const int wn   = wid >> 1;
    const int row0 = blockIdx.x * 64;
    const int gq = lane >> 2, tg = lane & 3;

    const uint32_t sAb = smem_u32(Asb), sBb = smem_u32(Bsb);
    const uint32_t a_rel = (uint32_t)(((wm * 32 + (lane & 15)) * LDA
                                       + (lane >> 4) * 8) * 2);
    uint32_t b_rel[3];
#pragma unroll
    for (int p = 0; p < 3; p++)
        b_rel[p] = (uint32_t)(((wn * 48 + p * 16 + (lane & 7) + ((lane >> 4) << 3)) * LDA
                              + ((lane >> 3) & 1) * 8) * 2);

    float acc[2][6][4];
#pragma unroll
    for (int mi = 0; mi < 2; mi++)
#pragma unroll
        for (int ni = 0; ni < 6; ni++)
#pragma unroll
            for (int j = 0; j < 4; j++) acc[mi][ni][j] = 0.f;

    const int nstages = 6;

    auto prefetch = [&](int s, int b) {
        const bf16* Bg = Bt + (size_t)s * 32;
        uint32_t sA = sAb + (uint32_t)b * (ASZ * 2);
        uint32_t sB = sBb + (uint32_t)b * (BSZ * 2);
        {
            int r = tid >> 2, c4 = tid & 3;
            int rg = row0 + r;
            int win = rg / 24, n2 = rg - win * 24;
            const bf16* src = A + ((size_t)win * 6 + s) * 768 + n2 * 32 + c4 * 8;
            cp16(sA + (uint32_t)(r * 80 + c4 * 16), src);
        }
#pragma unroll
        for (int j = 0; j < 3; j++) {
            int idx = tid + j * 256;
            int r = idx >> 2, c = idx & 3;
            cp16(sB + (uint32_t)(r * 80 + c * 16), Bg + (size_t)r * K + c * 8);
        }
        CP_COMMIT();
    };

    prefetch(0, 0);
    prefetch(1, 1);

    for (int s = 0; s < nstages; s++) {
        if (s < nstages - 1) CP_WAIT(1); else CP_WAIT(0);
        __syncthreads();
        if (s + 2 < nstages) prefetch(s + 2, (s + 2) % 3);

        const int b = s % 3;
        const uint32_t sA = sAb + (uint32_t)b * (ASZ * 2) + a_rel;
        const uint32_t sBB = sBb + (uint32_t)b * (BSZ * 2);
#pragma unroll
        for (int kk = 0; kk < 32; kk += 16) {
            uint32_t afr[2][4];
#pragma unroll
            for (int mi = 0; mi < 2; mi++)
                ldsm_x4(afr[mi], sA + (uint32_t)(kk * 2 + mi * (16 * LDA * 2)));

            uint32_t bfr[6][2];
#pragma unroll
            for (int p = 0; p < 3; p++) {
                uint32_t r4[4];
                ldsm_x4(r4, sBB + b_rel[p] + (uint32_t)(kk * 2));
                bfr[2*p][0] = r4[0]; bfr[2*p][1] = r4[1];
                bfr[2*p+1][0] = r4[2]; bfr[2*p+1][1] = r4[3];
            }
#pragma unroll
            for (int mi = 0; mi < 2; mi++)
#pragma unroll
                for (int ni = 0; ni < 6; ni++)
                    mma_bf16(acc[mi][ni], afr[mi], bfr[ni], acc[mi][ni]);
        }
    }

    // ---- epilogue: bias + residual(from x) + row stats ----
#pragma unroll
    for (int mi = 0; mi < 2; mi++) {
#pragma unroll
        for (int hh = 0; hh < 2; hh++) {
            int rl = wm * 32 + mi * 16 + gq + hh * 8;
            int r  = row0 + rl;
            size_t roff = token_src_offset(r);
            float s1 = 0.f, s2 = 0.f;
#pragma unroll
            for (int ni = 0; ni < 6; ni++) {
                int col = wn * 48 + ni * 8 + tg * 2;
                float2 rx = *(const float2*)(x + roff + col);
                float v0 = acc[mi][ni][hh*2]     + bias[col]     + rx.x;
                float v1 = acc[mi][ni][hh*2 + 1] + bias[col + 1] + rx.y;
                acc[mi][ni][hh*2]     = v0;
                acc[mi][ni][hh*2 + 1] = v1;
                s1 += v0 + v1;
                s2 += v0 * v0 + v1 * v1;
            }
            s1 += __shfl_xor_sync(0xffffffffu, s1, 1);
            s1 += __shfl_xor_sync(0xffffffffu, s1, 2);
            s2 += __shfl_xor_sync(0xffffffffu, s2, 1);
            s2 += __shfl_xor_sync(0xffffffffu, s2, 2);
            if (tg == 0) { s_sum[rl][wn] = s1; s_sq[rl][wn] = s2; }
        }
    }
    __syncthreads();
#pragma unroll
    for (int mi = 0; mi < 2; mi++) {
#pragma unroll
        for (int hh = 0; hh < 2; hh++) {
            int rl = wm * 32 + mi * 16 + gq + hh * 8;
            int r  = row0 + rl;
            float S1 = s_sum[rl][0] + s_sum[rl][1] + s_sum[rl][2] + s_sum[rl][3];
            float S2 = s_sq [rl][0] + s_sq [rl][1] + s_sq [rl][2] + s_sq [rl][3];
            float mean = S1 * (1.0f / 192.0f);
            float var  = S2 * (1.0f / 192.0f) - mean * mean;
            float rstd = rsqrtf(var + 1e-5f);
#pragma unroll
            for (int ni = 0; ni < 6; ni++) {
                int col = wn * 48 + ni * 8 + tg * 2;
                float v0 = acc[mi][ni][hh*2], v1 = acc[mi][ni][hh*2 + 1];
                *(float2*)(g_x2 + (size_t)r * 192 + col) = make_float2(v0, v1);
                float n0 = (v0 - mean) * rstd * gam[col]     + bet[col];
                float n1 = (v1 - mean) * rstd * gam[col + 1] + bet[col + 1];
                *(__nv_bfloat162*)(g_h + (size_t)r * 192 + col) =
                    __floats2bfloat162_rn(n0, n1);
            }
        }
    }
}

// ---------------- host launcher ----------------
extern "C" void kernel_launch(void* const* d_in, const int* in_sizes, int n_in,
                              void* d_out, int out_size)
{
    const float* x      = (const float*)d_in[0];
    const float* ln1_g  = (const float*)d_in[1];
    const float* ln1_b  = (const float*)d_in[2];
    const float* qkv_w  = (const float*)d_in[3];
    const float* qkv_b  = (const float*)d_in[4];
    const float* btab   = (const float*)d_in[5];
    const float* proj_w = (const float*)d_in[6];
    const float* proj_b = (const float*)d_in[7];
    const float* ln2_g  = (const float*)d_in[8];
    const float* ln2_b  = (const float*)d_in[9];
    const float* mlp_w1 = (const float*)d_in[10];
    const float* mlp_b1 = (const float*)d_in[11];
    const float* mlp_w2 = (const float*)d_in[12];
    const float* mlp_b2 = (const float*)d_in[13];
    const int*   rel_idx= (const int*)d_in[14];
    float*       out    = (float*)d_out;

    bf16 *p_h, *p_qkv, *p_attn, *p_hid;
    float *p_x2;
    bf16 *p_qkv_wt, *p_proj_wt, *p_w1t, *p_w2t;
    cudaGetSymbolAddress((void**)&p_h,    g_h);
    cudaGetSymbolAddress((void**)&p_qkv,  g_qkv);
    cudaGetSymbolAddress((void**)&p_attn, g_attn);
    cudaGetSymbolAddress((void**)&p_x2,   g_x2);
    cudaGetSymbolAddress((void**)&p_hid,  g_hid);
    cudaGetSymbolAddress((void**)&p_qkv_wt,  g_qkv_wt);
    cudaGetSymbolAddress((void**)&p_proj_wt, g_proj_wt);
    cudaGetSymbolAddress((void**)&p_w1t,  g_w1t);
    cudaGetSymbolAddress((void**)&p_w2t,  g_w2t);

    cudaFuncSetAttribute(tc_gemm<0>, cudaFuncAttributeMaxDynamicSharedMemorySize, GEMM_SMEM);
    cudaFuncSetAttribute(tc_gemm<1>, cudaFuncAttributeMaxDynamicSharedMemorySize, GEMM_SMEM);
    cudaFuncSetAttribute(tc_gemm<3>, cudaFuncAttributeMaxDynamicSharedMemorySize, GEMM_SMEM);
    cudaFuncSetAttribute(proj_ln2_kernel, cudaFuncAttributeMaxDynamicSharedMemorySize, PROJ_SMEM);

    transpose_all_kernel<<<432, dim3(32, 8)>>>(qkv_w, proj_w, mlp_w1, mlp_w2,
                                               p_qkv_wt, p_proj_wt, p_w1t, p_w2t);
    bias_precompute_kernel<<<HEADS, 576>>>(btab, rel_idx);

    gather_ln1_kernel<<<NTOK_TOTAL / 8, 256>>>(x, ln1_g, ln1_b);

    const int Mb = NTOK_TOTAL / 128;  // 1008
    tc_gemm<0><<<dim3(6, Mb), 256, GEMM_SMEM>>>(p_h, p_qkv_wt, qkv_b, nullptr, p_qkv, 576, 192);
    attn_kernel<<<NWIN * HEADS / 8, 256>>>();
    proj_ln2_kernel<<<NTOK_TOTAL / 64, 256, PROJ_SMEM>>>(p_attn, p_proj_wt, proj_b, x, ln2_g, ln2_b);
    tc_gemm<1><<<dim3(8, Mb), 256, GEMM_SMEM>>>(p_h, p_w1t, mlp_b1, nullptr, p_hid, 768, 192);
    tc_gemm<3><<<dim3(2, Mb), 256, GEMM_SMEM>>>(p_hid, p_w2t, mlp_b2, p_x2, out, 192, 768);
}

// round 14
// speedup vs baseline: 1.0230x; 1.0013x over previous
#include <cuda_runtime.h>
#include <cuda_bf16.h>
#include <math.h>
#include <stdint.h>

typedef __nv_bfloat16 bf16;
typedef unsigned long long u64;

// ---------------- problem constants ----------------
#define NTOK_TOTAL 129024   // 5376 windows * 24 tokens
#define NWIN       5376
#define HEADS      6

// ---------------- scratch (device globals) ----------------
__device__ float g_x2  [(size_t)NTOK_TOTAL * 192];
__device__ bf16  g_h   [(size_t)NTOK_TOTAL * 192];
__device__ bf16  g_qkv [(size_t)NTOK_TOTAL * 576];   // [win][head][q|k|v][24][32]
__device__ bf16  g_attn[(size_t)NTOK_TOTAL * 192];   // [win][head][24][32]
__device__ bf16  g_hid [(size_t)NTOK_TOTAL * 768];
__device__ float g_bias6[HEADS * 576];                // bias[h][m][n]
__device__ bf16 g_qkv_wt [576 * 192];
__device__ bf16 g_proj_wt[192 * 192];
__device__ bf16 g_w1t    [768 * 192];
__device__ bf16 g_w2t    [192 * 768];

// ---------------- helpers ----------------
__device__ __forceinline__ size_t token_src_offset(int t) {
    int wi = t / 24, n = t % 24;
    int i3 = n / 12, j3 = (n >> 1) % 6, k3 = n & 1;
    int d0 = wi % 7;  int r = wi / 7;
    int w0 = r % 16;  r /= 16;
    int h0 = r % 24;  int b0 = r / 24;
    return ((((size_t)b0 * 48 + (h0 * 2 + i3)) * 96 + (w0 * 6 + j3)) * 14
            + (d0 * 2 + k3)) * 192;
}
__device__ __forceinline__ float warp_sum(float v) {
#pragma unroll
    for (int o = 16; o; o >>= 1) v += __shfl_xor_sync(0xffffffffu, v, o);
    return v;
}
__device__ __forceinline__ uint32_t smem_u32(const void* p) {
    uint32_t a;
    asm("{ .reg .u64 t; cvta.to.shared.u64 t, %1; cvt.u32.u64 %0, t; }" : "=r"(a) : "l"(p));
    return a;
}
__device__ __forceinline__ void cp16(uint32_t dst, const void* src) {
    asm volatile("cp.async.cg.shared.global [%0], [%1], 16;" :: "r"(dst), "l"(src));
}
#define CP_COMMIT() asm volatile("cp.async.commit_group;" ::: "memory")
#define CP_WAIT(n)  asm volatile("cp.async.wait_group %0;" :: "n"(n) : "memory")

__device__ __forceinline__ void ldsm_x4(uint32_t* r, uint32_t a) {
    asm volatile("ldmatrix.sync.aligned.m8n8.x4.shared.b16 {%0,%1,%2,%3}, [%4];"
                 : "=r"(r[0]), "=r"(r[1]), "=r"(r[2]), "=r"(r[3]) : "r"(a));
}
__device__ __forceinline__ void mma_bf16(float* d, const uint32_t* a,
                                         const uint32_t* b, const float* c) {
    asm volatile(
        "mma.sync.aligned.m16n8k16.row.col.f32.bf16.bf16.f32 "
        "{%0,%1,%2,%3}, {%4,%5,%6,%7}, {%8,%9}, {%10,%11,%12,%13};"
        : "=f"(d[0]), "=f"(d[1]), "=f"(d[2]), "=f"(d[3])
        : "r"(a[0]), "r"(a[1]), "r"(a[2]), "r"(a[3]),
          "r"(b[0]), "r"(b[1]),
          "f"(c[0]), "f"(c[1]), "f"(c[2]), "f"(c[3]));
}
__device__ __forceinline__ float2 bf2f2(uint32_t u) {
    __nv_bfloat162 b = *reinterpret_cast<__nv_bfloat162*>(&u);
    return __bfloat1622float2(b);
}
__device__ __forceinline__ uint32_t f2bf2u(float lo, float hi) {
    __nv_bfloat162 b = __floats2bfloat162_rn(lo, hi);
    return *reinterpret_cast<uint32_t*>(&b);
}
// packed fp32x2 (Blackwell)
__device__ __forceinline__ u64 pack2(float lo, float hi) {
    u64 r; asm("mov.b64 %0, {%1, %2};" : "=l"(r) : "f"(lo), "f"(hi)); return r;
}
__device__ __forceinline__ void unpack2(u64 v, float& lo, float& hi) {
    asm("mov.b64 {%0, %1}, %2;" : "=f"(lo), "=f"(hi) : "l"(v));
}
__device__ __forceinline__ u64 fma2(u64 a, u64 b, u64 c) {
    u64 d; asm("fma.rn.f32x2 %0, %1, %2, %3;" : "=l"(d) : "l"(a), "l"(b), "l"(c));
    return d;
}

// ============ fused prep: weight transposes + bias + gather/LN1 ============
// blocks [0,432): transpose  [432,446): bias6  [446, 446+16128): gather+LN1
__global__ __launch_bounds__(256) void prep_kernel(
    const float* __restrict__ qkv_w, const float* __restrict__ proj_w,
    const float* __restrict__ w1, const float* __restrict__ w2,
    const float* __restrict__ bias_table, const int* __restrict__ rel_index,
    const float* __restrict__ x, const float* __restrict__ gam,
    const float* __restrict__ bet)
{
    int bid = blockIdx.x;
    if (bid < 432) {
        __shared__ float t[32][33];
        const float* W; bf16* Wt; int K, N, loc;
        if (bid < 108)      { W = qkv_w;  Wt = g_qkv_wt;  K = 192; N = 576; loc = bid; }
        else if (bid < 144) { W = proj_w; Wt = g_proj_wt; K = 192; N = 192; loc = bid - 108; }
        else if (bid < 288) { W = w1;     Wt = g_w1t;     K = 192; N = 768; loc = bid - 144; }
        else                { W = w2;     Wt = g_w2t;     K = 768; N = 192; loc = bid - 288; }
        int Kt = K / 32;
        int kb = (loc % Kt) * 32, nb = (loc / Kt) * 32;
        int xx = threadIdx.x & 31, yy = threadIdx.x >> 5;  // 32x8
#pragma unroll
        for (int j = 0; j < 32; j += 8) t[yy + j][xx] = W[(size_t)(kb + yy + j) * N + nb + xx];
        __syncthreads();
#pragma unroll
        for (int j = 0; j < 32; j += 8)
            Wt[(size_t)(nb + yy + j) * K + kb + xx] = __float2bfloat16(t[xx][yy + j]);
    } else if (bid < 446) {
        int idx = (bid - 432) * 256 + threadIdx.x;   // over 6*576 = 3456
        if (idx < HEADS * 576) {
            int h = idx / 576, rem = idx - h * 576;
            int m = rem / 24, n = rem - m * 24;
            g_bias6[h * 576 + rem] = bias_table[rel_index[n * 24 + m] * HEADS + h];
        }
    } else {
        int t = (bid - 446) * 8 + (threadIdx.x >> 5);
        int lane = threadIdx.x & 31;
        size_t src = token_src_offset(t);
        float v[6]; float s = 0.f;
#pragma unroll
        for (int q = 0; q < 6; q++) { v[q] = x[src + lane + q * 32]; s += v[q]; }
        float mean = warp_sum(s) * (1.0f / 192.0f);
        float vs = 0.f;
#pragma unroll
        for (int q = 0; q < 6; q++) { float d = v[q] - mean; vs += d * d; }
        float rstd = rsqrtf(warp_sum(vs) * (1.0f / 192.0f) + 1e-5f);
        size_t dst = (size_t)t * 192;
#pragma unroll
        for (int q = 0; q < 6; q++) {
            int c = lane + q * 32;
            g_h[dst + c] = __float2bfloat16((v[q] - mean) * rstd * gam[c] + bet[c]);
        }
    }
}

// ---------------- attention: packed f32x2 math, shfl-free softmax -----------
__global__ __launch_bounds__(256) void attn_kernel()
{
    __shared__ __align__(16) float k_s[8][768];   // [m*32 + d]
    __shared__ __align__(16) float v_s[8][768];
    const int w = threadIdx.x >> 5, lane = threadIdx.x & 31;
    const int pair = blockIdx.x * 8 + w;
    const int h = pair % 6;
    const bf16* base = g_qkv + (size_t)pair * 2304;   // [q 768 | k 768 | v 768]
    const float* bias = g_bias6 + h * 576;            // [m][n]

#pragma unroll
    for (int j = 0; j < 3; j++) {
        int idx = (lane + j * 32) * 8;
        uint4 uk = *(const uint4*)(base + 768 + idx);
        uint4 uv = *(const uint4*)(base + 1536 + idx);
        float2 f;
        f = bf2f2(uk.x); k_s[w][idx+0] = f.x; k_s[w][idx+1] = f.y;
        f = bf2f2(uk.y); k_s[w][idx+2] = f.x; k_s[w][idx+3] = f.y;
        f = bf2f2(uk.z); k_s[w][idx+4] = f.x; k_s[w][idx+5] = f.y;
        f = bf2f2(uk.w); k_s[w][idx+6] = f.x; k_s[w][idx+7] = f.y;
        f = bf2f2(uv.x); v_s[w][idx+0] = f.x; v_s[w][idx+1] = f.y;
        f = bf2f2(uv.y); v_s[w][idx+2] = f.x; v_s[w][idx+3] = f.y;
        f = bf2f2(uv.z); v_s[w][idx+4] = f.x; v_s[w][idx+5] = f.y;
        f = bf2f2(uv.w); v_s[w][idx+6] = f.x; v_s[w][idx+7] = f.y;
    }
    __syncwarp();

    if (lane < 24) {
        const float scale = 0.17677669529663687f;  // 32^-0.5
        // q row 'lane' -> packed f32x2 registers (scale folded in)
        u64 q2[16];
        const bf16* qp = base + lane * 32;
#pragma unroll
        for (int d = 0; d < 32; d += 8) {
            uint4 u = *(const uint4*)(qp + d);
            float2 f;
            f = bf2f2(u.x); q2[(d>>1)+0] = pack2(f.x*scale, f.y*scale);
            f = bf2f2(u.y); q2[(d>>1)+1] = pack2(f.x*scale, f.y*scale);
            f = bf2f2(u.z); q2[(d>>1)+2] = pack2(f.x*scale, f.y*scale);
            f = bf2f2(u.w); q2[(d>>1)+3] = pack2(f.x*scale, f.y*scale);
        }

        float p[24];
        float mx = -1e30f;
#pragma unroll 4
        for (int m = 0; m < 24; m++) {
            const u64* k2p = (const u64*)&k_s[w][m * 32];
            u64 acc = pack2(0.f, 0.f);
#pragma unroll
            for (int i = 0; i < 16; i++) acc = fma2(q2[i], k2p[i], acc);
            float ax, ay; unpack2(acc, ax, ay);
            float a = ax + ay + bias[m * 24 + lane];
            p[m] = a;
            mx = fmaxf(mx, a);
        }
        float sm = 0.f;
#pragma unroll
        for (int m = 0; m < 24; m++) { p[m] = __expf(p[m] - mx); sm += p[m]; }
        float inv = 1.0f / sm;

        // PV with packed accumulators over d-pairs
        u64 o2[16];
        const u64 z = pack2(0.f, 0.f);
#pragma unroll
        for (int i = 0; i < 16; i++) o2[i] = z;
#pragma unroll 4
        for (int m = 0; m < 24; m++) {
            u64 pm2 = pack2(p[m], p[m]);
            const u64* v2p = (const u64*)&v_s[w][m * 32];
#pragma unroll
            for (int i = 0; i < 16; i++) o2[i] = fma2(pm2, v2p[i], o2[i]);
        }
        bf16* ob = g_attn + (size_t)pair * 768 + lane * 32;
#pragma unroll
        for (int i = 0; i < 16; i += 4) {
            float a0,a1,b0,b1,c0,c1,d0,d1;
            unpack2(o2[i],   a0, a1); unpack2(o2[i+1], b0, b1);
            unpack2(o2[i+2], c0, c1); unpack2(o2[i+3], d0, d1);
            uint4 u;
            u.x = f2bf2u(a0*inv, a1*inv);
            u.y = f2bf2u(b0*inv, b1*inv);
            u.z = f2bf2u(c0*inv, c1*inv);
            u.w = f2bf2u(d0*inv, d1*inv);
            *(uint4*)(ob + i * 2) = u;
        }
    }
}

// ======================= generic bf16 GEMM (BN=96) ==========================
#define GEMM_SMEM (3 * (128 + 96) * 40 * 2)
template <int EPI>
__global__ __launch_bounds__(256, 3) void tc_gemm(
    const bf16* __restrict__ A, const bf16* __restrict__ Bt,
    const float* __restrict__ bias, const float* __restrict__ res,
    void* __restrict__ Cc, int N, int K)
{
    constexpr int LDA = 40;
    constexpr int ASZ = 128 * LDA, BSZ = 96 * LDA;
    extern __shared__ bf16 smem[];
    bf16* Asb = smem;
    bf16* Bsb = smem + 3 * ASZ;

    const int tid  = threadIdx.x;
    const int lane = tid & 31;
    const int wid  = tid >> 5;
    const int wm   = wid & 3;
    const int wn   = wid >> 2;
    const int col0 = blockIdx.x * 96;
    const int row0 = blockIdx.y * 128;
    const int gq = lane >> 2, tg = lane & 3;

    const uint32_t sAb = smem_u32(Asb), sBb = smem_u32(Bsb);
    const uint32_t a_rel = (uint32_t)(((wm * 32 + (lane & 15)) * LDA
                                       + (lane >> 4) * 8) * 2);
    uint32_t b_rel[3];
#pragma unroll
    for (int p = 0; p < 3; p++)
        b_rel[p] = (uint32_t)(((wn * 48 + p * 16 + (lane & 7) + ((lane >> 4) << 3)) * LDA
                              + ((lane >> 3) & 1) * 8) * 2);
    const int cr0 = tid >> 2, cr1 = (tid + 256) >> 2, cc = (tid & 3);
    const uint32_t cpa0 = (uint32_t)(cr0 * 80 + cc * 16);
    const uint32_t cpa1 = (uint32_t)(cr1 * 80 + cc * 16);

    float acc[2][6][4];
#pragma unroll
    for (int mi = 0; mi < 2; mi++)
#pragma unroll
        for (int ni = 0; ni < 6; ni++)
#pragma unroll
            for (int j = 0; j < 4; j++) acc[mi][ni][j] = 0.f;

    const int nstages = K / 32;

    auto prefetch = [&](int s, int b) {
        const bf16* Ag = A + (size_t)row0 * K + s * 32 + cc * 8;
        const bf16* Bg = Bt + (size_t)col0 * K + s * 32 + cc * 8;
        uint32_t sA = sAb + (uint32_t)b * (ASZ * 2);
        uint32_t sB = sBb + (uint32_t)b * (BSZ * 2);
        cp16(sA + cpa0, Ag + (size_t)cr0 * K);
        cp16(sA + cpa1, Ag + (size_t)cr1 * K);
        cp16(sB + cpa0, Bg + (size_t)cr0 * K);
        if (tid < 128)
            cp16(sB + cpa1, Bg + (size_t)cr1 * K);
        CP_COMMIT();
    };

    prefetch(0, 0);
    prefetch(1, 1);

    for (int s = 0; s < nstages; s++) {
        if (s < nstages - 1) CP_WAIT(1); else CP_WAIT(0);
        __syncthreads();
        if (s + 2 < nstages) prefetch(s + 2, (s + 2) % 3);

        const int b = s % 3;
        const uint32_t sA = sAb + (uint32_t)b * (ASZ * 2) + a_rel;
        const uint32_t sBB = sBb + (uint32_t)b * (BSZ * 2);
#pragma unroll
        for (int kk = 0; kk < 32; kk += 16) {
            uint32_t afr[2][4];
#pragma unroll
            for (int mi = 0; mi < 2; mi++)
                ldsm_x4(afr[mi], sA + (uint32_t)(kk * 2 + mi * (16 * LDA * 2)));

            uint32_t bfr[6][2];
#pragma unroll
            for (int p = 0; p < 3; p++) {
                uint32_t r4[4];
                ldsm_x4(r4, sBB + b_rel[p] + (uint32_t)(kk * 2));
                bfr[2*p][0] = r4[0]; bfr[2*p][1] = r4[1];
                bfr[2*p+1][0] = r4[2]; bfr[2*p+1][1] = r4[3];
            }
#pragma unroll
            for (int mi = 0; mi < 2; mi++)
#pragma unroll
                for (int ni = 0; ni < 6; ni++)
                    mma_bf16(acc[mi][ni], afr[mi], bfr[ni], acc[mi][ni]);
        }
    }

#pragma unroll
    for (int mi = 0; mi < 2; mi++) {
#pragma unroll
        for (int ni = 0; ni < 6; ni++) {
            int row = row0 + wm * 32 + mi * 16 + gq;
            int col = col0 + wn * 48 + ni * 8 + tg * 2;
            float b0 = bias[col], b1 = bias[col + 1];
#pragma unroll
            for (int hh = 0; hh < 2; hh++) {
                int r = row + hh * 8;
                float v0 = acc[mi][ni][hh * 2]     + b0;
                float v1 = acc[mi][ni][hh * 2 + 1] + b1;
                if (EPI == 1) {
                    v0 = 0.5f * v0 * (1.0f + erff(v0 * 0.70710678118654752f));
                    v1 = 0.5f * v1 * (1.0f + erff(v1 * 0.70710678118654752f));
                }
                if (EPI == 0) {
                    int wi2 = r / 24, n2 = r - wi2 * 24;
                    int which = col / 192;
                    int rem = col - which * 192;
                    int h2 = rem >> 5, d2 = rem & 31;
                    bf16* cp_ = (bf16*)Cc +
                        ((((size_t)wi2 * 6 + h2) * 3 + which) * 768 + n2 * 32 + d2);
                    *(__nv_bfloat162*)cp_ = __floats2bfloat162_rn(v0, v1);
                } else if (EPI == 3) {
                    const float* rp = res + (size_t)r * 192 + col;
                    v0 += rp[0]; v1 += rp[1];
                    size_t off = token_src_offset(r) + col;
                    *(float2*)((float*)Cc + off) = make_float2(v0, v1);
                } else {
                    bf16* cp_ = (bf16*)Cc + (size_t)r * N + col;
                    *(__nv_bfloat162*)cp_ = __floats2bfloat162_rn(v0, v1);
                }
            }
        }
    }
}

// ===== proj GEMM (BM=64, BN=192) + residual(from x) + LN2, 3 CTAs/SM ========
#define PROJ_SMEM (3 * (64 + 192) * 40 * 2)
__global__ __launch_bounds__(256, 3) void proj_ln2_kernel(
    const bf16* __restrict__ A, const bf16* __restrict__ Bt,
    const float* __restrict__ bias, const float* __restrict__ x,
    const float* __restrict__ gam, const float* __restrict__ bet)
{
    constexpr int LDA = 40, K = 192;
    constexpr int ASZ = 64 * LDA, BSZ = 192 * LDA;
    extern __shared__ bf16 smem[];
    bf16* Asb = smem;
    bf16* Bsb = smem + 3 * ASZ;
    __shared__ float s_sum[64][4];
    __shared__ float s_sq [64][4];

    const int tid  = threadIdx.x;
    const int lane = tid & 31;
    const int wid  = tid >> 5;
    const int wm   = wid & 1;
    const int wn   = wid >> 1;
    const int row0 = blockIdx.x * 64;
    const int gq = lane >> 2, tg = lane & 3;

    const uint32_t sAb = smem_u32(Asb), sBb = smem_u32(Bsb);
    const uint32_t a_rel = (uint32_t)(((wm * 32 + (lane & 15)) * LDA
                                       + (lane >> 4) * 8) * 2);
    uint32_t b_rel[3];
#pragma unroll
    for (int p = 0; p < 3; p++)
        b_rel[p] = (uint32_t)(((wn * 48 + p * 16 + (lane & 7) + ((lane >> 4) << 3)) * LDA
                              + ((lane >> 3) & 1) * 8) * 2);

    float acc[2][6][4];
#pragma unroll
    for (int mi = 0; mi < 2; mi++)
#pragma unroll
        for (int ni = 0; ni < 6; ni++)
#pragma unroll
            for (int j = 0; j < 4; j++) acc[mi][ni][j] = 0.f;

    const int nstages = 6;

    auto prefetch = [&](int s, int b) {
        const bf16* Bg = Bt + (size_t)s * 32;
        uint32_t sA = sAb + (uint32_t)b * (ASZ * 2);
        uint32_t sB = sBb + (uint32_t)b * (BSZ * 2);
        {
            int r = tid >> 2, c4 = tid & 3;
            int rg = row0 + r;
            int win = rg / 24, n2 = rg - win * 24;
            const bf16* src = A + ((size_t)win * 6 + s) * 768 + n2 * 32 + c4 * 8;
            cp16(sA + (uint32_t)(r * 80 + c4 * 16), src);
        }
#pragma unroll
        for (int j = 0; j < 3; j++) {
            int idx = tid + j * 256;
            int r = idx >> 2, c = idx & 3;
            cp16(sB + (uint32_t)(r * 80 + c * 16), Bg + (size_t)r * K + c * 8);
        }
        CP_COMMIT();
    };

    prefetch(0, 0);
    prefetch(1, 1);

    for (int s = 0; s < nstages; s++) {
        if (s < nstages - 1) CP_WAIT(1); else CP_WAIT(0);
        __syncthreads();
        if (s + 2 < nstages) prefetch(s + 2, (s + 2) % 3);

        const int b = s % 3;
        const uint32_t sA = sAb + (uint32_t)b * (ASZ * 2) + a_rel;
        const uint32_t sBB = sBb + (uint32_t)b * (BSZ * 2);
#pragma unroll
        for (int kk = 0; kk < 32; kk += 16) {
            uint32_t afr[2][4];
#pragma unroll
            for (int mi = 0; mi < 2; mi++)
                ldsm_x4(afr[mi], sA + (uint32_t)(kk * 2 + mi * (16 * LDA * 2)));

            uint32_t bfr[6][2];
#pragma unroll
            for (int p = 0; p < 3; p++) {
                uint32_t r4[4];
                ldsm_x4(r4, sBB + b_rel[p] + (uint32_t)(kk * 2));
                bfr[2*p][0] = r4[0]; bfr[2*p][1] = r4[1];
                bfr[2*p+1][0] = r4[2]; bfr[2*p+1][1] = r4[3];
            }
#pragma unroll
            for (int mi = 0; mi < 2; mi++)
#pragma unroll
                for (int ni = 0; ni < 6; ni++)
                    mma_bf16(acc[mi][ni], afr[mi], bfr[ni], acc[mi][ni]);
        }
    }

#pragma unroll
    for (int mi = 0; mi < 2; mi++) {
#pragma unroll
        for (int hh = 0; hh < 2; hh++) {
            int rl = wm * 32 + mi * 16 + gq + hh * 8;
            int r  = row0 + rl;
            size_t roff = token_src_offset(r);
            float s1 = 0.f, s2 = 0.f;
#pragma unroll
            for (int ni = 0; ni < 6; ni++) {
                int col = wn * 48 + ni * 8 + tg * 2;
                float2 rx = *(const float2*)(x + roff + col);
                float v0 = acc[mi][ni][hh*2]     + bias[col]     + rx.x;
                float v1 = acc[mi][ni][hh*2 + 1] + bias[col + 1] + rx.y;
                acc[mi][ni][hh*2]     = v0;
                acc[mi][ni][hh*2 + 1] = v1;
                s1 += v0 + v1;
                s2 += v0 * v0 + v1 * v1;
            }
            s1 += __shfl_xor_sync(0xffffffffu, s1, 1);
            s1 += __shfl_xor_sync(0xffffffffu, s1, 2);
            s2 += __shfl_xor_sync(0xffffffffu, s2, 1);
            s2 += __shfl_xor_sync(0xffffffffu, s2, 2);
            if (tg == 0) { s_sum[rl][wn] = s1; s_sq[rl][wn] = s2; }
        }
    }
    __syncthreads();
#pragma unroll
    for (int mi = 0; mi < 2; mi++) {
#pragma unroll
        for (int hh = 0; hh < 2; hh++) {
            int rl = wm * 32 + mi * 16 + gq + hh * 8;
            int r  = row0 + rl;
            float S1 = s_sum[rl][0] + s_sum[rl][1] + s_sum[rl][2] + s_sum[rl][3];
            float S2 = s_sq [rl][0] + s_sq [rl][1] + s_sq [rl][2] + s_sq [rl][3];
            float mean = S1 * (1.0f / 192.0f);
            float var  = S2 * (1.0f / 192.0f) - mean * mean;
            float rstd = rsqrtf(var + 1e-5f);
#pragma unroll
            for (int ni = 0; ni < 6; ni++) {
                int col = wn * 48 + ni * 8 + tg * 2;
                float v0 = acc[mi][ni][hh*2], v1 = acc[mi][ni][hh*2 + 1];
                *(float2*)(g_x2 + (size_t)r * 192 + col) = make_float2(v0, v1);
                float n0 = (v0 - mean) * rstd * gam[col]     + bet[col];
                float n1 = (v1 - mean) * rstd * gam[col + 1] + bet[col + 1];
                *(__nv_bfloat162*)(g_h + (size_t)r * 192 + col) =
                    __floats2bfloat162_rn(n0, n1);
            }
        }
    }
}

// ---------------- host launcher ----------------
extern "C" void kernel_launch(void* const* d_in, const int* in_sizes, int n_in,
                              void* d_out, int out_size)
{
    const float* x      = (const float*)d_in[0];
    const float* ln1_g  = (const float*)d_in[1];
    const float* ln1_b  = (const float*)d_in[2];
    const float* qkv_w  = (const float*)d_in[3];
    const float* qkv_b  = (const float*)d_in[4];
    const float* btab   = (const float*)d_in[5];
    const float* proj_w = (const float*)d_in[6];
    const float* proj_b = (const float*)d_in[7];
    const float* ln2_g  = (const float*)d_in[8];
    const float* ln2_b  = (const float*)d_in[9];
    const float* mlp_w1 = (const float*)d_in[10];
    const float* mlp_b1 = (const float*)d_in[11];
    const float* mlp_w2 = (const float*)d_in[12];
    const float* mlp_b2 = (const float*)d_in[13];
    const int*   rel_idx= (const int*)d_in[14];
    float*       out    = (float*)d_out;

    bf16 *p_h, *p_qkv, *p_attn, *p_hid;
    float *p_x2;
    bf16 *p_qkv_wt, *p_proj_wt, *p_w1t, *p_w2t;
    cudaGetSymbolAddress((void**)&p_h,    g_h);
    cudaGetSymbolAddress((void**)&p_qkv,  g_qkv);
    cudaGetSymbolAddress((void**)&p_attn, g_attn);
    cudaGetSymbolAddress((void**)&p_x2,   g_x2);
    cudaGetSymbolAddress((void**)&p_hid,  g_hid);
    cudaGetSymbolAddress((void**)&p_qkv_wt,  g_qkv_wt);
    cudaGetSymbolAddress((void**)&p_proj_wt, g_proj_wt);
    cudaGetSymbolAddress((void**)&p_w1t,  g_w1t);
    cudaGetSymbolAddress((void**)&p_w2t,  g_w2t);

    cudaFuncSetAttribute(tc_gemm<0>, cudaFuncAttributeMaxDynamicSharedMemorySize, GEMM_SMEM);
    cudaFuncSetAttribute(tc_gemm<1>, cudaFuncAttributeMaxDynamicSharedMemorySize, GEMM_SMEM);
    cudaFuncSetAttribute(tc_gemm<3>, cudaFuncAttributeMaxDynamicSharedMemorySize, GEMM_SMEM);
    cudaFuncSetAttribute(proj_ln2_kernel, cudaFuncAttributeMaxDynamicSharedMemorySize, PROJ_SMEM);

    // fused prep: transposes + bias + gather/LN1
    prep_kernel<<<446 + NTOK_TOTAL / 8, 256>>>(qkv_w, proj_w, mlp_w1, mlp_w2,
                                               btab, rel_idx, x, ln1_g, ln1_b);

    const int Mb = NTOK_TOTAL / 128;  // 1008
    tc_gemm<0><<<dim3(6, Mb), 256, GEMM_SMEM>>>(p_h, p_qkv_wt, qkv_b, nullptr, p_qkv, 576, 192);
    attn_kernel<<<NWIN * HEADS / 8, 256>>>();
    proj_ln2_kernel<<<NTOK_TOTAL / 64, 256, PROJ_SMEM>>>(p_attn, p_proj_wt, proj_b, x, ln2_g, ln2_b);
    tc_gemm<1><<<dim3(8, Mb), 256, GEMM_SMEM>>>(p_h, p_w1t, mlp_b1, nullptr, p_hid, 768, 192);
    tc_gemm<3><<<dim3(2, Mb), 256, GEMM_SMEM>>>(p_hid, p_w2t, mlp_b2, p_x2, out, 192, 768);
}